// round 14
// baseline (speedup 1.0000x reference)
#include <cuda_runtime.h>
#include <cuda_bf16.h>
#include <cuda_fp16.h>
#include <math.h>
#include <stdint.h>

#define TT 256
#define HIDN 256
#define G3 768
#define D2 512
#define D8 2048
#define S1 128
#define S2 64
#define M1 256
#define M2 128

#define PL_X   ((size_t)S1*TT*HIDN)
#define PL_W1  ((size_t)2*G3*HIDN)
#define PL_W2  ((size_t)2*G3*D8)
#define PL_HC  ((size_t)S1*TT*D2)
#define PL_H2  ((size_t)S2*TT*D2)
#define PL_CSC ((size_t)S2*TT*D2)
#define PL_SC  ((size_t)S2*TT*TT)
#define PL_ATT ((size_t)S2*TT*D8)

// ---------------- static device scratch ----------------
__device__ float g_gi1  [(size_t)2*S1*TT*G3];
__device__ float g_hcat [(size_t)S1*TT*D2];
__device__ float g_h2out[(size_t)S2*TT*D2];
__device__ float g_gi2  [(size_t)2*S2*TT*G3];
__device__ float g_att  [(size_t)S2*TT*D8];
__device__ float g_Sc   [(size_t)S2*TT*TT];
__device__ float g_cw   [S2*TT];
__device__ float g_qw   [S2*TT];
__device__ float g_mrow [S2*TT];
__device__ float g_q2c  [S2*D2];
__device__ float g_part [32*64];

// fp16 single planes (feed-forward GEMM operands)
__device__ __half g_xh   [PL_X];
__device__ __half g_w1h  [PL_W1];
__device__ __half g_w2h  [PL_W2];
__device__ __half g_hch  [PL_HC];
__device__ __half g_h2h  [PL_H2];
__device__ __half g_csch [PL_CSC];
__device__ __half g_sch  [PL_SC];
__device__ __half g_atth [PL_ATT];

// ---------------- generic helpers ----------------
__device__ __forceinline__ float blk_sum(float v, float* red) {
    int t = threadIdx.x;
    red[t] = v; __syncthreads();
    for (int o = blockDim.x >> 1; o > 0; o >>= 1) {
        if (t < o) red[t] += red[t + o];
        __syncthreads();
    }
    float r = red[0]; __syncthreads();
    return r;
}
__device__ __forceinline__ float blk_max(float v, float* red) {
    int t = threadIdx.x;
    red[t] = v; __syncthreads();
    for (int o = blockDim.x >> 1; o > 0; o >>= 1) {
        if (t < o) red[t] = fmaxf(red[t], red[t + o]);
        __syncthreads();
    }
    float r = red[0]; __syncthreads();
    return r;
}
__device__ __forceinline__ float sigm(float x) { return 1.f / (1.f + __expf(-x)); }

__device__ __forceinline__ void cluster_sync_() {
    asm volatile("barrier.cluster.arrive.aligned;" ::: "memory");
    asm volatile("barrier.cluster.wait.aligned;" ::: "memory");
}

// ---------------- split-bf16 helpers (scan only) ----------------
__device__ __forceinline__ uint32_t pk2(__nv_bfloat16 a, __nv_bfloat16 b) {
    return (uint32_t)__bfloat16_as_ushort(a) | ((uint32_t)__bfloat16_as_ushort(b) << 16);
}
__device__ __forceinline__ void split8(const float* f, uint4& hi, uint4& lo) {
    __nv_bfloat16 h[8]; float l[8];
#pragma unroll
    for (int i = 0; i < 8; i++) {
        h[i] = __float2bfloat16(f[i]);
        l[i] = f[i] - __bfloat162float(h[i]);
    }
    hi = make_uint4(pk2(h[0],h[1]), pk2(h[2],h[3]), pk2(h[4],h[5]), pk2(h[6],h[7]));
    lo = make_uint4(pk2(__float2bfloat16(l[0]),__float2bfloat16(l[1])),
                    pk2(__float2bfloat16(l[2]),__float2bfloat16(l[3])),
                    pk2(__float2bfloat16(l[4]),__float2bfloat16(l[5])),
                    pk2(__float2bfloat16(l[6]),__float2bfloat16(l[7])));
}

#define LDMX4(r0,r1,r2,r3,addr) \
    asm volatile("ldmatrix.sync.aligned.m8n8.x4.shared.b16 {%0,%1,%2,%3}, [%4];" \
        : "=r"(r0), "=r"(r1), "=r"(r2), "=r"(r3) : "r"(addr))
#define LDMX4T(r0,r1,r2,r3,addr) \
    asm volatile("ldmatrix.sync.aligned.m8n8.x4.trans.shared.b16 {%0,%1,%2,%3}, [%4];" \
        : "=r"(r0), "=r"(r1), "=r"(r2), "=r"(r3) : "r"(addr))

#define MMABF(c0,c1,c2,c3,a0,a1,a2,a3,b0,b1) \
    asm volatile("mma.sync.aligned.m16n8k16.row.col.f32.bf16.bf16.f32 " \
        "{%0,%1,%2,%3}, {%4,%5,%6,%7}, {%8,%9}, {%0,%1,%2,%3};" \
        : "+f"(c0), "+f"(c1), "+f"(c2), "+f"(c3) \
        : "r"(a0), "r"(a1), "r"(a2), "r"(a3), "r"(b0), "r"(b1))

#define MMAHF(c0,c1,c2,c3,a0,a1,a2,a3,b0,b1) \
    asm volatile("mma.sync.aligned.m16n8k16.row.col.f32.f16.f16.f32 " \
        "{%0,%1,%2,%3}, {%4,%5,%6,%7}, {%8,%9}, {%0,%1,%2,%3};" \
        : "+f"(c0), "+f"(c1), "+f"(c2), "+f"(c3) \
        : "r"(a0), "r"(a1), "r"(a2), "r"(a3), "r"(b0), "r"(b1))

#define CPA16(dst, src) \
    asm volatile("cp.async.cg.shared.global [%0], [%1], 16;" :: "r"(dst), "l"(src))
#define CPA_COMMIT() asm volatile("cp.async.commit_group;" ::: "memory")
#define CPA_WAIT0()  asm volatile("cp.async.wait_group 0;" ::: "memory")

// ---------------- conversion kernels ----------------
__global__ void conv_w(const float* __restrict__ w, __half* __restrict__ dst, int n)
{
    int i = blockIdx.x * 256 + threadIdx.x;
    if (i < n) dst[i] = __float2half(w[i]);
}

__global__ void __launch_bounds__(256) gather_embed(
    const int* __restrict__ q, const int* __restrict__ a,
    const float* __restrict__ emb)
{
    int t = blockIdx.x, s = blockIdx.y, tid = threadIdx.x;
    int id = (s < 64) ? q[(s >> 1) * TT + t] : a[(size_t)(s - 64) * TT + t];
    float v = emb[(size_t)id * HIDN + tid];
    g_xh[((size_t)s * TT + t) * HIDN + tid] = __float2half(v);
}

// ---------------- pipelined fp16 single-term MMA GEMM, BM=128 BN=128 ----------------
#define SKP 40
#define PLANEH (128 * SKP)
#define STAGEH (2 * PLANEH)
#define GH_SMEM (2 * STAGEH * 2)

__global__ void __launch_bounds__(256, 2) gemm_hf(
    const __half* __restrict__ Ab, long long sA,
    const __half* __restrict__ Wb, long long sW,
    float* __restrict__ Cb, long long sC,
    int N, int K, int foldN,
    const float* __restrict__ bias, long long sBias,
    const float* __restrict__ cw, const float* __restrict__ qw,
    const float* __restrict__ bvec)
{
    extern __shared__ __half smx[];
    const int tid = threadIdx.x;
    const int wid = tid >> 5, lane = tid & 31;
    const int z = blockIdx.z;
    const int m0 = blockIdx.y * 128, n0 = blockIdx.x * 128;
    const __half* A = Ab + (size_t)z * sA;
    const __half* W = Wb + (size_t)z * sW;

    const int wm = (wid & 3) * 32;
    const int wn = (wid >> 2) * 64;
    const int nk = K >> 5;

    const int r0 = tid >> 2, cg8 = (tid & 3) * 8;

    float acc[2][8][4];
#pragma unroll
    for (int i = 0; i < 2; i++)
#pragma unroll
        for (int j = 0; j < 8; j++)
#pragma unroll
            for (int qq = 0; qq < 4; qq++) acc[i][j][qq] = 0.f;

    const int lrow = ((lane >> 3) & 1) * 8 + (lane & 7);
    const int lk8 = (lane >> 4) * 8;

    auto issue = [&](int ki, int st) {
        const int k0 = ki * 32;
        __half* Ast = smx + st * STAGEH;
        __half* Bst = Ast + PLANEH;
#pragma unroll
        for (int half_ = 0; half_ < 2; half_++) {
            int r = r0 + half_ * 64;
            size_t ao = (size_t)(m0 + r) * K + k0 + cg8;
            size_t bo = (size_t)(n0 + r) * K + k0 + cg8;
            uint32_t da = (uint32_t)__cvta_generic_to_shared(&Ast[r * SKP + cg8]);
            uint32_t db = (uint32_t)__cvta_generic_to_shared(&Bst[r * SKP + cg8]);
            CPA16(da, A + ao);
            CPA16(db, W + bo);
        }
    };

    issue(0, 0);
    CPA_COMMIT();

    for (int ki = 0; ki < nk; ki++) {
        const int st = ki & 1;
        CPA_WAIT0();
        __syncthreads();
        if (ki + 1 < nk) { issue(ki + 1, st ^ 1); CPA_COMMIT(); }

        __half* Ast = smx + st * STAGEH;
        __half* Bst = Ast + PLANEH;
#pragma unroll
        for (int kk = 0; kk < 32; kk += 16) {
            uint32_t aF[2][4];
#pragma unroll
            for (int mi = 0; mi < 2; mi++) {
                uint32_t ad = (uint32_t)__cvta_generic_to_shared(
                    &Ast[(wm + mi * 16 + lrow) * SKP + kk + lk8]);
                LDMX4(aF[mi][0], aF[mi][1], aF[mi][2], aF[mi][3], ad);
            }
            uint32_t bF[4][4];
#pragma unroll
            for (int nj2 = 0; nj2 < 4; nj2++) {
                uint32_t ad = (uint32_t)__cvta_generic_to_shared(
                    &Bst[(wn + nj2 * 16 + lrow) * SKP + kk + lk8]);
                LDMX4(bF[nj2][0], bF[nj2][1], bF[nj2][2], bF[nj2][3], ad);
            }
#pragma unroll
            for (int mi = 0; mi < 2; mi++)
#pragma unroll
                for (int nj = 0; nj < 8; nj++) {
                    int nj2 = nj >> 1, odd = nj & 1;
                    MMAHF(acc[mi][nj][0], acc[mi][nj][1], acc[mi][nj][2], acc[mi][nj][3],
                          aF[mi][0], aF[mi][1], aF[mi][2], aF[mi][3],
                          bF[nj2][odd], bF[nj2][2 + odd]);
                }
        }
    }
    const int g = lane >> 2, t4 = lane & 3;
    if (bias) {
        const int zz = (n0 >= foldN) ? 1 : 0;
        const int nb = n0 - zz * foldN;
        float* C = Cb + (size_t)zz * sC;
        const float* bz = bias + (size_t)zz * sBias;
#pragma unroll
        for (int mi = 0; mi < 2; mi++) {
            int mrow = m0 + wm + mi * 16 + g;
#pragma unroll
            for (int nj = 0; nj < 8; nj++) {
                int ncol = nb + wn + nj * 8 + t4 * 2;
                float b0v = bz[ncol];
                float b1v = bz[ncol + 1];
                *(float2*)&C[(size_t)mrow * foldN + ncol] =
                    make_float2(acc[mi][nj][0] + b0v, acc[mi][nj][1] + b1v);
                *(float2*)&C[(size_t)(mrow + 8) * foldN + ncol] =
                    make_float2(acc[mi][nj][2] + b0v, acc[mi][nj][3] + b1v);
            }
        }
    } else {
        float* C = Cb + (size_t)z * sC;
        float badd = bvec[0] + bvec[1] + bvec[2];
#pragma unroll
        for (int mi = 0; mi < 2; mi++) {
            int mrow = m0 + wm + mi * 16 + g;
            float cw0 = cw[(size_t)z * TT + mrow] + badd;
            float cw1 = cw[(size_t)z * TT + mrow + 8] + badd;
#pragma unroll
            for (int nj = 0; nj < 8; nj++) {
                int ncol = n0 + wn + nj * 8 + t4 * 2;
                float q0v = qw[(size_t)z * TT + ncol];
                float q1v = qw[(size_t)z * TT + ncol + 1];
                *(float2*)&C[(size_t)mrow * N + ncol] =
                    make_float2(acc[mi][nj][0] + cw0 + q0v, acc[mi][nj][1] + cw0 + q1v);
                *(float2*)&C[(size_t)(mrow + 8) * N + ncol] =
                    make_float2(acc[mi][nj][2] + cw1 + q0v, acc[mi][nj][3] + cw1 + q1v);
            }
        }
    }
}

// ---------------- pipelined c2q fp16: probs @ q (trans B) + BiDAF epilogue ----------------
#define C2_AST (128 * SKP)
#define BKP 72
#define B2ST (32 * BKP)
#define C2STAGE (C2_AST + B2ST)
#define C2Q_SMEM (2 * C2STAGE * 2)

__global__ void __launch_bounds__(256) gemm_c2q_h(
    const __half* __restrict__ Ab,
    const __half* __restrict__ Bb, long long sB,
    const float* __restrict__ cb, long long sCrow,
    float* __restrict__ outb, __half* __restrict__ atth, int addMode)
{
    extern __shared__ __half smx[];
    const int tid = threadIdx.x;
    const int wid = tid >> 5, lane = tid & 31;
    const int z = blockIdx.z;
    const int m0 = blockIdx.y * 128, n0 = blockIdx.x * 64;
    const __half* A = Ab + (size_t)z * TT * TT;
    const __half* B = Bb + (size_t)z * sB;
    const float* c = cb + (size_t)z * sCrow;
    const float* qc = g_q2c + (size_t)z * D2;
    float* out = outb + (size_t)z * TT * D8;

    const int wm = (wid & 3) * 32;
    const int wn = (wid >> 2) * 32;

    float acc[2][4][4];
#pragma unroll
    for (int i = 0; i < 2; i++)
#pragma unroll
        for (int j = 0; j < 4; j++)
#pragma unroll
            for (int qq = 0; qq < 4; qq++) acc[i][j][qq] = 0.f;

    const int lrow = ((lane >> 3) & 1) * 8 + (lane & 7);
    const int lk8 = (lane >> 4) * 8;
    const int lkrow = (lane & 7) + ((lane >> 4) << 3);
    const int lncol = ((lane >> 3) & 1) * 8;

    const int ar0 = tid >> 2, acg = (tid & 3) * 8;
    const int bkr = tid >> 3, bnc = (tid & 7) * 8;

    auto issue = [&](int ki, int st) {
        const int k0 = ki * 32;
        __half* Ast = smx + st * C2STAGE;
        __half* Bst = Ast + C2_AST;
#pragma unroll
        for (int half_ = 0; half_ < 2; half_++) {
            int r = ar0 + half_ * 64;
            size_t so = (size_t)(m0 + r) * TT + k0 + acg;
            uint32_t d = (uint32_t)__cvta_generic_to_shared(&Ast[r * SKP + acg]);
            CPA16(d, A + so);
        }
        {
            size_t so = (size_t)(k0 + bkr) * D2 + n0 + bnc;
            uint32_t d = (uint32_t)__cvta_generic_to_shared(&Bst[bkr * BKP + bnc]);
            CPA16(d, B + so);
        }
    };

    issue(0, 0);
    CPA_COMMIT();

    for (int ki = 0; ki < (TT >> 5); ki++) {
        const int st = ki & 1;
        CPA_WAIT0();
        __syncthreads();
        if (ki + 1 < (TT >> 5)) { issue(ki + 1, st ^ 1); CPA_COMMIT(); }

        __half* Ast = smx + st * C2STAGE;
        __half* Bst = Ast + C2_AST;
#pragma unroll
        for (int kk = 0; kk < 32; kk += 16) {
            uint32_t aF[2][4], bF[2][4];
#pragma unroll
            for (int mi = 0; mi < 2; mi++) {
                uint32_t ad = (uint32_t)__cvta_generic_to_shared(
                    &Ast[(wm + mi * 16 + lrow) * SKP + kk + lk8]);
                LDMX4(aF[mi][0], aF[mi][1], aF[mi][2], aF[mi][3], ad);
            }
#pragma unroll
            for (int nj2 = 0; nj2 < 2; nj2++) {
                uint32_t ad = (uint32_t)__cvta_generic_to_shared(
                    &Bst[(kk + lkrow) * BKP + wn + nj2 * 16 + lncol]);
                LDMX4T(bF[nj2][0], bF[nj2][1], bF[nj2][2], bF[nj2][3], ad);
            }
#pragma unroll
            for (int mi = 0; mi < 2; mi++)
#pragma unroll
                for (int nj = 0; nj < 4; nj++) {
                    int nj2 = nj >> 1, odd = nj & 1;
                    MMAHF(acc[mi][nj][0], acc[mi][nj][1], acc[mi][nj][2], acc[mi][nj][3],
                          aF[mi][0], aF[mi][1], aF[mi][2], aF[mi][3],
                          bF[nj2][odd], bF[nj2][2 + odd]);
                }
        }
    }
    const int g = lane >> 2, t4 = lane & 3;
#pragma unroll
    for (int mi = 0; mi < 2; mi++) {
#pragma unroll
        for (int nj = 0; nj < 4; nj++) {
#pragma unroll
            for (int hh = 0; hh < 4; hh++) {
                int mm = m0 + wm + mi * 16 + g + (hh >> 1) * 8;
                int nn = n0 + wn + nj * 8 + t4 * 2 + (hh & 1);
                float c2v = acc[mi][nj][hh];
                float cv = c[(size_t)mm * D2 + nn];
                float o0 = fmaxf(cv, 0.f);
                float o1 = fmaxf(c2v, 0.f);
                float o2 = fmaxf(cv * c2v, 0.f);
                float o3 = fmaxf(cv * qc[nn], 0.f);
                size_t b = (size_t)mm * D8 + nn;
                if (addMode) {
                    out[b] += o0; out[b + 512] += o1;
                    out[b + 1024] += o2; out[b + 1536] += o3;
                } else {
                    out[b] = o0; out[b + 512] = o1;
                    out[b + 1024] = o2; out[b + 1536] = o3;
                    size_t ab = (size_t)z * TT * D8 + b;
                    atth[ab]        = __float2half(o0);
                    atth[ab + 512]  = __float2half(o1);
                    atth[ab + 1024] = __float2half(o2);
                    atth[ab + 1536] = __float2half(o3);
                }
            }
        }
    }
}

// ---------------- tensor-core persistent GRU scan (cluster-8, bf16 3-term) ----------------
#define ABST 264
#define ABUF (16 * ABST)
#define OFF_BHI 0
#define OFF_BLO (96 * ABST * 2)
#define OFF_A   (OFF_BLO + 96 * ABST * 2)
#define OFF_GHS (OFF_A + 4 * ABUF * 2)
#define OFF_GIS (OFF_GHS + 16 * 104 * 4)
#define SCAN2_SMEM (OFF_GIS + 16 * 104 * 4)

__global__ void __cluster_dims__(8, 1, 1) __launch_bounds__(256)
gru_scan_mma(const float* __restrict__ gi, const float* __restrict__ whh,
             const float* __restrict__ bhh, float* __restrict__ seqout,
             __half* __restrict__ seqh, int S)
{
    extern __shared__ char smraw[];
    __nv_bfloat16* Bhi = (__nv_bfloat16*)(smraw + OFF_BHI);
    __nv_bfloat16* Blo = (__nv_bfloat16*)(smraw + OFF_BLO);
    __nv_bfloat16* Ab  = (__nv_bfloat16*)(smraw + OFF_A);
    float* ghs = (float*)(smraw + OFF_GHS);
    float* gis = (float*)(smraw + OFF_GIS);

    const int tid = threadIdx.x;
    const int wid = tid >> 5, lane = tid & 31;
    const int j0 = blockIdx.x * 32;
    const int myrank = blockIdx.x & 7;
    const int m0 = blockIdx.y * 16;
    const int dd = m0 / S;
    const int jj = tid & 31, j = j0 + jj;
    const int r0 = (tid >> 5) * 2;

    const float* wb = whh + (size_t)dd * G3 * HIDN;
    for (int task = tid; task < 96 * 32; task += 256) {
        int row = task >> 5, grp = task & 31;
        int g = row >> 5, cc = row & 31;
        const float* src = wb + (size_t)(g * 256 + j0 + cc) * HIDN + grp * 8;
        float f[8];
        *(float4*)&f[0] = *(const float4*)src;
        *(float4*)&f[4] = *(const float4*)(src + 4);
        uint4 hi, lo; split8(f, hi, lo);
        *(uint4*)&Bhi[row * ABST + grp * 8] = hi;
        *(uint4*)&Blo[row * ABST + grp * 8] = lo;
    }
    for (int i = tid; i < 4 * ABUF / 2; i += 256)
        ((uint32_t*)Ab)[i] = 0;

    const float b0 = bhh[(size_t)dd * G3 + j];
    const float b1 = bhh[(size_t)dd * G3 + 256 + j];
    const float b2 = bhh[(size_t)dd * G3 + 512 + j];

    uint32_t abase = (uint32_t)__cvta_generic_to_shared(Ab);
    uint32_t peer[8];
#pragma unroll
    for (int rk = 0; rk < 8; rk++)
        asm volatile("mapa.shared::cluster.u32 %0, %1, %2;" : "=r"(peer[rk]) : "r"(abase), "r"(rk));

    const int lrow = ((lane >> 3) & 1) * 8 + (lane & 7);
    const int lk8 = (lane >> 4) * 8;

    // broadcast-unit assignment: plane, stream, quad (4 j's) within own slice
    const int bplane = tid >> 7;
    const int brem = tid & 127;
    const int bs = brem >> 3, bq = brem & 7;

    cluster_sync_();

    for (int t = 0; t < TT; t++) {
        const int cur = t & 1, nxt = cur ^ 1;
        const int tq = dd ? (TT - 1 - t) : t;

        if (wid < 6) {
            const __nv_bfloat16* Ahi = Ab + (cur * 2 + 0) * ABUF;
            const __nv_bfloat16* Alo = Ab + (cur * 2 + 1) * ABUF;
            float acc[2][4] = {{0,0,0,0},{0,0,0,0}};
#pragma unroll
            for (int kt = 0; kt < 16; kt++) {
                uint32_t aF[2][4], bF[2][4];
                uint32_t adh = (uint32_t)__cvta_generic_to_shared(
                    &Ahi[lrow * ABST + kt * 16 + lk8]);
                uint32_t adl = (uint32_t)__cvta_generic_to_shared(
                    &Alo[lrow * ABST + kt * 16 + lk8]);
                LDMX4(aF[0][0], aF[0][1], aF[0][2], aF[0][3], adh);
                LDMX4(aF[1][0], aF[1][1], aF[1][2], aF[1][3], adl);
                uint32_t bdh = (uint32_t)__cvta_generic_to_shared(
                    &Bhi[(wid * 16 + lrow) * ABST + kt * 16 + lk8]);
                uint32_t bdl = (uint32_t)__cvta_generic_to_shared(
                    &Blo[(wid * 16 + lrow) * ABST + kt * 16 + lk8]);
                LDMX4(bF[0][0], bF[0][1], bF[0][2], bF[0][3], bdh);
                LDMX4(bF[1][0], bF[1][1], bF[1][2], bF[1][3], bdl);
#pragma unroll
                for (int term = 0; term < 3; term++) {
                    const int sa = (term == 2) ? 1 : 0;
                    const int sb = (term == 1) ? 1 : 0;
#pragma unroll
                    for (int nj = 0; nj < 2; nj++)
                        MMABF(acc[nj][0], acc[nj][1], acc[nj][2], acc[nj][3],
                              aF[sa][0], aF[sa][1], aF[sa][2], aF[sa][3],
                              bF[sb][nj], bF[sb][2 + nj]);
                }
            }
            int gr = lane >> 2, c2 = (lane & 3) * 2;
#pragma unroll
            for (int nj = 0; nj < 2; nj++) {
                int col = wid * 16 + nj * 8 + c2;
                *(float2*)&ghs[gr * 104 + col] = make_float2(acc[nj][0], acc[nj][1]);
                *(float2*)&ghs[(gr + 8) * 104 + col] = make_float2(acc[nj][2], acc[nj][3]);
            }
        } else {
            int l2 = (wid - 6) * 32 + lane;
#pragma unroll
            for (int u = 0; u < 6; u++) {
                int f = l2 + u * 64;
                int seg = f >> 3, q = f & 7;
                int s = seg / 3, g = seg % 3;
                float4 v = *(const float4*)(gi + (size_t)(m0 + s) * TT * G3 +
                                            (size_t)tq * G3 + g * 256 + j0 + q * 4);
                *(float4*)&gis[s * 104 + g * 32 + q * 4] = v;
            }
        }
        __syncthreads();

        const __nv_bfloat16* AhiC = Ab + (cur * 2 + 0) * ABUF;
        const __nv_bfloat16* AloC = Ab + (cur * 2 + 1) * ABUF;
        __nv_bfloat16* AhN = Ab + (nxt * 2 + 0) * ABUF;
        __nv_bfloat16* AlN = Ab + (nxt * 2 + 1) * ABUF;
#pragma unroll
        for (int r = 0; r < 2; r++) {
            int s = r0 + r;
            float ir  = gis[s * 104 + jj];
            float iz  = gis[s * 104 + 32 + jj];
            float inn = gis[s * 104 + 64 + jj];
            float gr_ = ghs[s * 104 + jj];
            float gz_ = ghs[s * 104 + 32 + jj];
            float gn_ = ghs[s * 104 + 64 + jj];
            float rg = sigm(ir + gr_ + b0);
            float zg = sigm(iz + gz_ + b1);
            float ng = tanhf(inn + rg * (gn_ + b2));
            float hold = __bfloat162float(AhiC[s * ABST + j]) +
                         __bfloat162float(AloC[s * ABST + j]);
            float hnew = (1.f - zg) * ng + zg * hold;
            int sidx = m0 + s - dd * S;
            size_t so = ((size_t)sidx * TT + tq) * D2 + dd * HIDN + j;
            seqout[so] = hnew;
            seqh[so] = __float2half(hnew);
            __nv_bfloat16 hh = __float2bfloat16(hnew);
            __nv_bfloat16 hl = __float2bfloat16(hnew - __bfloat162float(hh));
            // local write only (own rank's slice)
            AhN[s * ABST + j] = hh;
            AlN[s * ABST + j] = hl;
        }
        __syncthreads();

        // broadcast own slice (as u64 quads) to the other 7 ranks
        {
            uint32_t off = (uint32_t)((nxt * 2 + bplane) * ABUF + bs * ABST + j0 + bq * 4) * 2;
            unsigned long long v =
                *(const unsigned long long*)((const char*)(const void*)Ab + off);
#pragma unroll
            for (int rk = 0; rk < 8; rk++) {
                if (rk != myrank)
                    asm volatile("st.shared::cluster.u64 [%0], %1;"
                                 :: "r"(peer[rk] + off), "l"(v) : "memory");
            }
        }
        cluster_sync_();
    }
}

// ---------------- BiDAF prep / softmax / q2c / rank ----------------
__global__ void __launch_bounds__(256) bidaf_prep(
    const float* __restrict__ cbase, const float* __restrict__ qbase,
    const float* __restrict__ w)
{
    __shared__ float red[256];
    int i = blockIdx.x, z = blockIdx.y, tid = threadIdx.x;
    const float* c = cbase + ((size_t)z * TT + i) * D2;
    const float* q = qbase + ((size_t)z * TT + i) * D2;
    float c0 = c[tid], c1 = c[tid + 256];
    float q0 = q[tid], q1 = q[tid + 256];
    float sc = c0 * w[tid] + c1 * w[tid + 256];
    float sq = q0 * w[512 + tid] + q1 * w[768 + tid];
    float cs0 = c0 * w[1024 + tid];
    float cs1 = c1 * w[1280 + tid];
    size_t ci = ((size_t)z * TT + i) * D2 + tid;
    g_csch[ci] = __float2half(cs0);
    g_csch[ci + 256] = __float2half(cs1);
    float rc = blk_sum(sc, red);
    float rq = blk_sum(sq, red);
    if (tid == 0) { g_cw[z * TT + i] = rc; g_qw[z * TT + i] = rq; }
}

__global__ void __launch_bounds__(256) softmax_row()
{
    __shared__ float red[256];
    int i = blockIdx.x, z = blockIdx.y, tid = threadIdx.x;
    const float* row = g_Sc + ((size_t)z * TT + i) * TT;
    float v = row[tid];
    float mx = blk_max(v, red);
    float e = __expf(v - mx);
    float sm = blk_sum(e, red);
    float p = e / sm;
    g_sch[((size_t)z * TT + i) * TT + tid] = __float2half(p);
    if (tid == 0) g_mrow[z * TT + i] = mx;
}

__global__ void __launch_bounds__(256) q2c_kern(const float* __restrict__ cbase)
{
    __shared__ float red[256];
    __shared__ float bbuf[256];
    int z = blockIdx.x, tid = threadIdx.x;
    float v = g_mrow[z * TT + tid];
    float mx = blk_max(v, red);
    float e = __expf(v - mx);
    float sm = blk_sum(e, red);
    bbuf[tid] = e / sm;
    __syncthreads();
    const float* c = cbase + (size_t)z * TT * D2;
    float a0 = 0.f, a1 = 0.f;
    for (int i = 0; i < TT; i++) {
        float b = bbuf[i];
        a0 += b * c[(size_t)i * D2 + tid];
        a1 += b * c[(size_t)i * D2 + tid + 256];
    }
    g_q2c[(size_t)z * D2 + tid] = a0;
    g_q2c[(size_t)z * D2 + tid + 256] = a1;
}

__global__ void __launch_bounds__(256) rank_partial(const float* __restrict__ rw)
{
    __shared__ float red[256];
    int chunk = blockIdx.x, bo = blockIdx.y, tid = threadIdx.x;
    const float* s0 = g_att + (size_t)(bo * 2) * TT * D8;
    const float* s1 = g_att + (size_t)(bo * 2 + 1) * TT * D8;
    float acc = 0.f;
    int e0 = chunk * 8192 + tid;
#pragma unroll 4
    for (int it = 0; it < 32; it++) {
        int e = e0 + it * 256;
        acc += fmaxf(s0[e], s1[e]) * rw[e];
    }
    float r = blk_sum(acc, red);
    if (tid == 0) g_part[bo * 64 + chunk] = r;
}

__global__ void rank_final(const float* __restrict__ rb, float* __restrict__ out)
{
    __shared__ float red[64];
    int bo = blockIdx.x, tid = threadIdx.x;
    red[tid] = g_part[bo * 64 + tid];
    __syncthreads();
    for (int o = 32; o > 0; o >>= 1) {
        if (tid < o) red[tid] += red[tid + o];
        __syncthreads();
    }
    if (tid == 0) out[bo] = red[0] + rb[0];
}

// ---------------- host ----------------
extern "C" void kernel_launch(void* const* d_in, const int* in_sizes, int n_in,
                              void* d_out, int out_size)
{
    const int*   question = (const int*)d_in[0];
    const int*   article  = (const int*)d_in[1];
    const float* emb      = (const float*)d_in[2];
    const float* g1_wih   = (const float*)d_in[3];
    const float* g1_whh   = (const float*)d_in[4];
    const float* g1_bih   = (const float*)d_in[5];
    const float* g1_bhh   = (const float*)d_in[6];
    const float* g2_wih   = (const float*)d_in[7];
    const float* g2_whh   = (const float*)d_in[8];
    const float* g2_bih   = (const float*)d_in[9];
    const float* g2_bhh   = (const float*)d_in[10];
    const float* b1_w     = (const float*)d_in[11];
    const float* b1_b     = (const float*)d_in[12];
    const float* b2_w     = (const float*)d_in[13];
    const float* b2_b     = (const float*)d_in[14];
    const float* rank_w   = (const float*)d_in[15];
    const float* rank_b   = (const float*)d_in[16];
    float* out = (float*)d_out;

    float *gi1, *gi2, *hcat, *h2out, *att, *Sc, *cwp, *qwp;
    __half *xh, *w1h, *w2h, *hch, *h2h, *csch, *sch, *atth;
    cudaGetSymbolAddress((void**)&gi1,  g_gi1);
    cudaGetSymbolAddress((void**)&gi2,  g_gi2);
    cudaGetSymbolAddress((void**)&hcat, g_hcat);
    cudaGetSymbolAddress((void**)&h2out,g_h2out);
    cudaGetSymbolAddress((void**)&att,  g_att);
    cudaGetSymbolAddress((void**)&Sc,   g_Sc);
    cudaGetSymbolAddress((void**)&cwp,  g_cw);
    cudaGetSymbolAddress((void**)&qwp,  g_qw);
    cudaGetSymbolAddress((void**)&xh,   g_xh);
    cudaGetSymbolAddress((void**)&w1h,  g_w1h);
    cudaGetSymbolAddress((void**)&w2h,  g_w2h);
    cudaGetSymbolAddress((void**)&hch,  g_hch);
    cudaGetSymbolAddress((void**)&h2h,  g_h2h);
    cudaGetSymbolAddress((void**)&csch, g_csch);
    cudaGetSymbolAddress((void**)&sch,  g_sch);
    cudaGetSymbolAddress((void**)&atth, g_atth);

    cudaFuncSetAttribute(gru_scan_mma, cudaFuncAttributeMaxDynamicSharedMemorySize, SCAN2_SMEM);
    cudaFuncSetAttribute(gemm_hf, cudaFuncAttributeMaxDynamicSharedMemorySize, GH_SMEM);
    cudaFuncSetAttribute(gemm_c2q_h, cudaFuncAttributeMaxDynamicSharedMemorySize, C2Q_SMEM);

    // 0. weight conversion
    conv_w<<<(int)((PL_W1 + 255) / 256), 256>>>(g1_wih, w1h, (int)PL_W1);
    conv_w<<<(int)((PL_W2 + 255) / 256), 256>>>(g2_wih, w2h, (int)PL_W2);

    // 1. embed
    gather_embed<<<dim3(TT, S1), 256>>>(question, article, emb);

    // 2. gi1 = xcat @ wih1^T + bih1 (z folded into N)
    gemm_hf<<<dim3(2*G3/128, (S1*TT)/128, 1), 256, GH_SMEM>>>(
        xh, 0LL, w1h, 0LL,
        gi1, (long long)S1*TT*G3, 2*G3, HIDN, G3,
        g1_bih, G3, nullptr, nullptr, nullptr);

    // 3. layer-1 scan
    gru_scan_mma<<<dim3(8, M1/16), 256, SCAN2_SMEM>>>(
        gi1, g1_whh, g1_bhh, hcat, hch, S1);

    // 4. BiDAF1
    const float* cb1 = hcat;
    const long long qoff = (long long)64 * TT * D2;
    bidaf_prep<<<dim3(TT, S2), 256>>>(cb1, hcat + qoff, b1_w);
    gemm_hf<<<dim3(TT/128, TT/128, S2), 256, GH_SMEM>>>(
        csch, (long long)TT*D2, hch + qoff, (long long)TT*D2,
        Sc, (long long)TT*TT, TT, D2, 0,
        nullptr, 0, cwp, qwp, b1_b);
    softmax_row<<<dim3(TT, S2), 256>>>();
    q2c_kern<<<S2, 256>>>(cb1);
    gemm_c2q_h<<<dim3(D2/64, TT/128, S2), 256, C2Q_SMEM>>>(
        sch, hch + qoff, (long long)TT*D2,
        cb1, (long long)TT*D2, att, atth, 0);

    // 5. gi2 = att @ wih2^T + bih2 (z folded)
    gemm_hf<<<dim3(2*G3/128, (S2*TT)/128, 1), 256, GH_SMEM>>>(
        atth, 0LL, w2h, 0LL,
        gi2, (long long)S2*TT*G3, 2*G3, D8, G3,
        g2_bih, G3, nullptr, nullptr, nullptr);

    // 6. layer-2 scan
    gru_scan_mma<<<dim3(8, M2/16), 256, SCAN2_SMEM>>>(
        gi2, g2_whh, g2_bhh, h2out, h2h, S2);

    // 7. BiDAF2
    bidaf_prep<<<dim3(TT, S2), 256>>>(h2out, h2out, b2_w);
    gemm_hf<<<dim3(TT/128, TT/128, S2), 256, GH_SMEM>>>(
        csch, (long long)TT*D2, h2h, (long long)TT*D2,
        Sc, (long long)TT*TT, TT, D2, 0,
        nullptr, 0, cwp, qwp, b2_b);
    softmax_row<<<dim3(TT, S2), 256>>>();
    q2c_kern<<<S2, 256>>>(h2out);
    gemm_c2q_h<<<dim3(D2/64, TT/128, S2), 256, C2Q_SMEM>>>(
        sch, h2h, (long long)TT*D2,
        h2out, (long long)TT*D2, att, atth, 1);

    // 8. rank
    rank_partial<<<dim3(64, 32), 256>>>(rank_w);
    rank_final<<<32, 64>>>(rank_b, out);
}

// round 15
// speedup vs baseline: 1.0944x; 1.0944x over previous
#include <cuda_runtime.h>
#include <cuda_bf16.h>
#include <cuda_fp16.h>
#include <math.h>
#include <stdint.h>

#define TT 256
#define HIDN 256
#define G3 768
#define D2 512
#define D8 2048
#define S1 128
#define S2 64
#define M1 256
#define M2 128

#define PL_X   ((size_t)S1*TT*HIDN)
#define PL_W1  ((size_t)2*G3*HIDN)
#define PL_W2  ((size_t)2*G3*D8)
#define PL_HC  ((size_t)S1*TT*D2)
#define PL_H2  ((size_t)S2*TT*D2)
#define PL_CSC ((size_t)S2*TT*D2)
#define PL_SC  ((size_t)S2*TT*TT)
#define PL_ATT ((size_t)S2*TT*D8)

// ---------------- static device scratch ----------------
__device__ float g_gi1  [(size_t)2*S1*TT*G3];
__device__ float g_hcat [(size_t)S1*TT*D2];
__device__ float g_h2out[(size_t)S2*TT*D2];
__device__ float g_gi2  [(size_t)2*S2*TT*G3];
__device__ float g_att  [(size_t)S2*TT*D8];
__device__ float g_Sc   [(size_t)S2*TT*TT];
__device__ float g_cw   [S2*TT];
__device__ float g_qw   [S2*TT];
__device__ float g_mrow [S2*TT];
__device__ float g_q2c  [S2*D2];
__device__ float g_part [32*64];

__device__ __half g_xh   [PL_X];
__device__ __half g_w1h  [PL_W1];
__device__ __half g_w2h  [PL_W2];
__device__ __half g_hch  [PL_HC];
__device__ __half g_h2h  [PL_H2];
__device__ __half g_csch [PL_CSC];
__device__ __half g_sch  [PL_SC];
__device__ __half g_atth [PL_ATT];

// ---------------- generic helpers ----------------
__device__ __forceinline__ float blk_sum(float v, float* red) {
    int t = threadIdx.x;
    red[t] = v; __syncthreads();
    for (int o = blockDim.x >> 1; o > 0; o >>= 1) {
        if (t < o) red[t] += red[t + o];
        __syncthreads();
    }
    float r = red[0]; __syncthreads();
    return r;
}
__device__ __forceinline__ float blk_max(float v, float* red) {
    int t = threadIdx.x;
    red[t] = v; __syncthreads();
    for (int o = blockDim.x >> 1; o > 0; o >>= 1) {
        if (t < o) red[t] = fmaxf(red[t], red[t + o]);
        __syncthreads();
    }
    float r = red[0]; __syncthreads();
    return r;
}
__device__ __forceinline__ float sigm(float x) { return 1.f / (1.f + __expf(-x)); }

__device__ __forceinline__ void cluster_sync_() {
    asm volatile("barrier.cluster.arrive.aligned;" ::: "memory");
    asm volatile("barrier.cluster.wait.aligned;" ::: "memory");
}

// ---------------- split-bf16 helpers (scan only) ----------------
__device__ __forceinline__ uint32_t pk2(__nv_bfloat16 a, __nv_bfloat16 b) {
    return (uint32_t)__bfloat16_as_ushort(a) | ((uint32_t)__bfloat16_as_ushort(b) << 16);
}
__device__ __forceinline__ void split8(const float* f, uint4& hi, uint4& lo) {
    __nv_bfloat16 h[8]; float l[8];
#pragma unroll
    for (int i = 0; i < 8; i++) {
        h[i] = __float2bfloat16(f[i]);
        l[i] = f[i] - __bfloat162float(h[i]);
    }
    hi = make_uint4(pk2(h[0],h[1]), pk2(h[2],h[3]), pk2(h[4],h[5]), pk2(h[6],h[7]));
    lo = make_uint4(pk2(__float2bfloat16(l[0]),__float2bfloat16(l[1])),
                    pk2(__float2bfloat16(l[2]),__float2bfloat16(l[3])),
                    pk2(__float2bfloat16(l[4]),__float2bfloat16(l[5])),
                    pk2(__float2bfloat16(l[6]),__float2bfloat16(l[7])));
}

#define LDMX4(r0,r1,r2,r3,addr) \
    asm volatile("ldmatrix.sync.aligned.m8n8.x4.shared.b16 {%0,%1,%2,%3}, [%4];" \
        : "=r"(r0), "=r"(r1), "=r"(r2), "=r"(r3) : "r"(addr))
#define LDMX4T(r0,r1,r2,r3,addr) \
    asm volatile("ldmatrix.sync.aligned.m8n8.x4.trans.shared.b16 {%0,%1,%2,%3}, [%4];" \
        : "=r"(r0), "=r"(r1), "=r"(r2), "=r"(r3) : "r"(addr))

#define MMABF(c0,c1,c2,c3,a0,a1,a2,a3,b0,b1) \
    asm volatile("mma.sync.aligned.m16n8k16.row.col.f32.bf16.bf16.f32 " \
        "{%0,%1,%2,%3}, {%4,%5,%6,%7}, {%8,%9}, {%0,%1,%2,%3};" \
        : "+f"(c0), "+f"(c1), "+f"(c2), "+f"(c3) \
        : "r"(a0), "r"(a1), "r"(a2), "r"(a3), "r"(b0), "r"(b1))

#define MMAHF(c0,c1,c2,c3,a0,a1,a2,a3,b0,b1) \
    asm volatile("mma.sync.aligned.m16n8k16.row.col.f32.f16.f16.f32 " \
        "{%0,%1,%2,%3}, {%4,%5,%6,%7}, {%8,%9}, {%0,%1,%2,%3};" \
        : "+f"(c0), "+f"(c1), "+f"(c2), "+f"(c3) \
        : "r"(a0), "r"(a1), "r"(a2), "r"(a3), "r"(b0), "r"(b1))

#define CPA16(dst, src) \
    asm volatile("cp.async.cg.shared.global [%0], [%1], 16;" :: "r"(dst), "l"(src))
#define CPA_COMMIT() asm volatile("cp.async.commit_group;" ::: "memory")
#define CPA_WAIT0()  asm volatile("cp.async.wait_group 0;" ::: "memory")
#define CPA_WAIT1()  asm volatile("cp.async.wait_group 1;" ::: "memory")
#define CPA_WAIT2()  asm volatile("cp.async.wait_group 2;" ::: "memory")

__device__ __forceinline__ void cpa_wait_rem(int rem) {
    if (rem >= 2) CPA_WAIT2();
    else if (rem == 1) CPA_WAIT1();
    else CPA_WAIT0();
}

// ---------------- conversion kernels ----------------
__global__ void conv_w(const float* __restrict__ w, __half* __restrict__ dst, int n)
{
    int i = blockIdx.x * 256 + threadIdx.x;
    if (i < n) dst[i] = __float2half(w[i]);
}

__global__ void __launch_bounds__(256) gather_embed(
    const int* __restrict__ q, const int* __restrict__ a,
    const float* __restrict__ emb)
{
    int t = blockIdx.x, s = blockIdx.y, tid = threadIdx.x;
    int id = (s < 64) ? q[(s >> 1) * TT + t] : a[(size_t)(s - 64) * TT + t];
    float v = emb[(size_t)id * HIDN + tid];
    g_xh[((size_t)s * TT + t) * HIDN + tid] = __float2half(v);
}

// ---------------- 4-stage pipelined fp16 MMA GEMM, BM=128 BN=128 ----------------
#define SKP 40
#define PLANEH (128 * SKP)
#define STAGEH (2 * PLANEH)
#define GH_SMEM (4 * STAGEH * 2)

__global__ void __launch_bounds__(256, 2) gemm_hf(
    const __half* __restrict__ Ab, long long sA,
    const __half* __restrict__ Wb, long long sW,
    float* __restrict__ Cb, long long sC,
    int N, int K, int foldN,
    const float* __restrict__ bias, long long sBias,
    const float* __restrict__ cw, const float* __restrict__ qw,
    const float* __restrict__ bvec)
{
    extern __shared__ __half smx[];
    const int tid = threadIdx.x;
    const int wid = tid >> 5, lane = tid & 31;
    const int z = blockIdx.z;
    const int m0 = blockIdx.y * 128, n0 = blockIdx.x * 128;
    const __half* A = Ab + (size_t)z * sA;
    const __half* W = Wb + (size_t)z * sW;

    const int wm = (wid & 3) * 32;
    const int wn = (wid >> 2) * 64;
    const int nk = K >> 5;

    const int r0 = tid >> 2, cg8 = (tid & 3) * 8;

    float acc[2][8][4];
#pragma unroll
    for (int i = 0; i < 2; i++)
#pragma unroll
        for (int j = 0; j < 8; j++)
#pragma unroll
            for (int qq = 0; qq < 4; qq++) acc[i][j][qq] = 0.f;

    const int lrow = ((lane >> 3) & 1) * 8 + (lane & 7);
    const int lk8 = (lane >> 4) * 8;

    auto issue = [&](int ki) {
        const int k0 = ki * 32;
        __half* Ast = smx + (ki & 3) * STAGEH;
        __half* Bst = Ast + PLANEH;
#pragma unroll
        for (int half_ = 0; half_ < 2; half_++) {
            int r = r0 + half_ * 64;
            size_t ao = (size_t)(m0 + r) * K + k0 + cg8;
            size_t bo = (size_t)(n0 + r) * K + k0 + cg8;
            uint32_t da = (uint32_t)__cvta_generic_to_shared(&Ast[r * SKP + cg8]);
            uint32_t db = (uint32_t)__cvta_generic_to_shared(&Bst[r * SKP + cg8]);
            CPA16(da, A + ao);
            CPA16(db, W + bo);
        }
    };

#pragma unroll
    for (int p = 0; p < 3; p++) {
        if (p < nk) { issue(p); CPA_COMMIT(); }
    }

    for (int ki = 0; ki < nk; ki++) {
        cpa_wait_rem(nk - ki - 1);
        __syncthreads();
        if (ki + 3 < nk) { issue(ki + 3); CPA_COMMIT(); }

        __half* Ast = smx + (ki & 3) * STAGEH;
        __half* Bst = Ast + PLANEH;
#pragma unroll
        for (int kk = 0; kk < 32; kk += 16) {
            uint32_t aF[2][4];
#pragma unroll
            for (int mi = 0; mi < 2; mi++) {
                uint32_t ad = (uint32_t)__cvta_generic_to_shared(
                    &Ast[(wm + mi * 16 + lrow) * SKP + kk + lk8]);
                LDMX4(aF[mi][0], aF[mi][1], aF[mi][2], aF[mi][3], ad);
            }
            uint32_t bF[4][4];
#pragma unroll
            for (int nj2 = 0; nj2 < 4; nj2++) {
                uint32_t ad = (uint32_t)__cvta_generic_to_shared(
                    &Bst[(wn + nj2 * 16 + lrow) * SKP + kk + lk8]);
                LDMX4(bF[nj2][0], bF[nj2][1], bF[nj2][2], bF[nj2][3], ad);
            }
#pragma unroll
            for (int mi = 0; mi < 2; mi++)
#pragma unroll
                for (int nj = 0; nj < 8; nj++) {
                    int nj2 = nj >> 1, odd = nj & 1;
                    MMAHF(acc[mi][nj][0], acc[mi][nj][1], acc[mi][nj][2], acc[mi][nj][3],
                          aF[mi][0], aF[mi][1], aF[mi][2], aF[mi][3],
                          bF[nj2][odd], bF[nj2][2 + odd]);
                }
        }
    }
    const int g = lane >> 2, t4 = lane & 3;
    if (bias) {
        const int zz = (n0 >= foldN) ? 1 : 0;
        const int nb = n0 - zz * foldN;
        float* C = Cb + (size_t)zz * sC;
        const float* bz = bias + (size_t)zz * sBias;
#pragma unroll
        for (int mi = 0; mi < 2; mi++) {
            int mrow = m0 + wm + mi * 16 + g;
#pragma unroll
            for (int nj = 0; nj < 8; nj++) {
                int ncol = nb + wn + nj * 8 + t4 * 2;
                float b0v = bz[ncol];
                float b1v = bz[ncol + 1];
                *(float2*)&C[(size_t)mrow * foldN + ncol] =
                    make_float2(acc[mi][nj][0] + b0v, acc[mi][nj][1] + b1v);
                *(float2*)&C[(size_t)(mrow + 8) * foldN + ncol] =
                    make_float2(acc[mi][nj][2] + b0v, acc[mi][nj][3] + b1v);
            }
        }
    } else {
        float* C = Cb + (size_t)z * sC;
        float badd = bvec[0] + bvec[1] + bvec[2];
#pragma unroll
        for (int mi = 0; mi < 2; mi++) {
            int mrow = m0 + wm + mi * 16 + g;
            float cw0 = cw[(size_t)z * TT + mrow] + badd;
            float cw1 = cw[(size_t)z * TT + mrow + 8] + badd;
#pragma unroll
            for (int nj = 0; nj < 8; nj++) {
                int ncol = n0 + wn + nj * 8 + t4 * 2;
                float q0v = qw[(size_t)z * TT + ncol];
                float q1v = qw[(size_t)z * TT + ncol + 1];
                *(float2*)&C[(size_t)mrow * N + ncol] =
                    make_float2(acc[mi][nj][0] + cw0 + q0v, acc[mi][nj][1] + cw0 + q1v);
                *(float2*)&C[(size_t)(mrow + 8) * N + ncol] =
                    make_float2(acc[mi][nj][2] + cw1 + q0v, acc[mi][nj][3] + cw1 + q1v);
            }
        }
    }
}

// ---------------- 4-stage pipelined c2q fp16 + BiDAF epilogue ----------------
#define C2_AST (128 * SKP)
#define BKP 72
#define B2ST (32 * BKP)
#define C2STAGE (C2_AST + B2ST)
#define C2Q_SMEM (4 * C2STAGE * 2)

__global__ void __launch_bounds__(256) gemm_c2q_h(
    const __half* __restrict__ Ab,
    const __half* __restrict__ Bb, long long sB,
    const float* __restrict__ cb, long long sCrow,
    float* __restrict__ outb, __half* __restrict__ atth, int addMode)
{
    extern __shared__ __half smx[];
    const int tid = threadIdx.x;
    const int wid = tid >> 5, lane = tid & 31;
    const int z = blockIdx.z;
    const int m0 = blockIdx.y * 128, n0 = blockIdx.x * 64;
    const __half* A = Ab + (size_t)z * TT * TT;
    const __half* B = Bb + (size_t)z * sB;
    const float* c = cb + (size_t)z * sCrow;
    const float* qc = g_q2c + (size_t)z * D2;
    float* out = outb + (size_t)z * TT * D8;

    const int wm = (wid & 3) * 32;
    const int wn = (wid >> 2) * 32;
    const int nk = TT >> 5;

    float acc[2][4][4];
#pragma unroll
    for (int i = 0; i < 2; i++)
#pragma unroll
        for (int j = 0; j < 4; j++)
#pragma unroll
            for (int qq = 0; qq < 4; qq++) acc[i][j][qq] = 0.f;

    const int lrow = ((lane >> 3) & 1) * 8 + (lane & 7);
    const int lk8 = (lane >> 4) * 8;
    const int lkrow = (lane & 7) + ((lane >> 4) << 3);
    const int lncol = ((lane >> 3) & 1) * 8;

    const int ar0 = tid >> 2, acg = (tid & 3) * 8;
    const int bkr = tid >> 3, bnc = (tid & 7) * 8;

    auto issue = [&](int ki) {
        const int k0 = ki * 32;
        __half* Ast = smx + (ki & 3) * C2STAGE;
        __half* Bst = Ast + C2_AST;
#pragma unroll
        for (int half_ = 0; half_ < 2; half_++) {
            int r = ar0 + half_ * 64;
            size_t so = (size_t)(m0 + r) * TT + k0 + acg;
            uint32_t d = (uint32_t)__cvta_generic_to_shared(&Ast[r * SKP + acg]);
            CPA16(d, A + so);
        }
        {
            size_t so = (size_t)(k0 + bkr) * D2 + n0 + bnc;
            uint32_t d = (uint32_t)__cvta_generic_to_shared(&Bst[bkr * BKP + bnc]);
            CPA16(d, B + so);
        }
    };

#pragma unroll
    for (int p = 0; p < 3; p++) {
        if (p < nk) { issue(p); CPA_COMMIT(); }
    }

    for (int ki = 0; ki < nk; ki++) {
        cpa_wait_rem(nk - ki - 1);
        __syncthreads();
        if (ki + 3 < nk) { issue(ki + 3); CPA_COMMIT(); }

        __half* Ast = smx + (ki & 3) * C2STAGE;
        __half* Bst = Ast + C2_AST;
#pragma unroll
        for (int kk = 0; kk < 32; kk += 16) {
            uint32_t aF[2][4], bF[2][4];
#pragma unroll
            for (int mi = 0; mi < 2; mi++) {
                uint32_t ad = (uint32_t)__cvta_generic_to_shared(
                    &Ast[(wm + mi * 16 + lrow) * SKP + kk + lk8]);
                LDMX4(aF[mi][0], aF[mi][1], aF[mi][2], aF[mi][3], ad);
            }
#pragma unroll
            for (int nj2 = 0; nj2 < 2; nj2++) {
                uint32_t ad = (uint32_t)__cvta_generic_to_shared(
                    &Bst[(kk + lkrow) * BKP + wn + nj2 * 16 + lncol]);
                LDMX4T(bF[nj2][0], bF[nj2][1], bF[nj2][2], bF[nj2][3], ad);
            }
#pragma unroll
            for (int mi = 0; mi < 2; mi++)
#pragma unroll
                for (int nj = 0; nj < 4; nj++) {
                    int nj2 = nj >> 1, odd = nj & 1;
                    MMAHF(acc[mi][nj][0], acc[mi][nj][1], acc[mi][nj][2], acc[mi][nj][3],
                          aF[mi][0], aF[mi][1], aF[mi][2], aF[mi][3],
                          bF[nj2][odd], bF[nj2][2 + odd]);
                }
        }
    }
    const int g = lane >> 2, t4 = lane & 3;
#pragma unroll
    for (int mi = 0; mi < 2; mi++) {
#pragma unroll
        for (int nj = 0; nj < 4; nj++) {
#pragma unroll
            for (int hh = 0; hh < 4; hh++) {
                int mm = m0 + wm + mi * 16 + g + (hh >> 1) * 8;
                int nn = n0 + wn + nj * 8 + t4 * 2 + (hh & 1);
                float c2v = acc[mi][nj][hh];
                float cv = c[(size_t)mm * D2 + nn];
                float o0 = fmaxf(cv, 0.f);
                float o1 = fmaxf(c2v, 0.f);
                float o2 = fmaxf(cv * c2v, 0.f);
                float o3 = fmaxf(cv * qc[nn], 0.f);
                size_t b = (size_t)mm * D8 + nn;
                if (addMode) {
                    out[b] += o0; out[b + 512] += o1;
                    out[b + 1024] += o2; out[b + 1536] += o3;
                } else {
                    out[b] = o0; out[b + 512] = o1;
                    out[b + 1024] = o2; out[b + 1536] = o3;
                    size_t ab = (size_t)z * TT * D8 + b;
                    atth[ab]        = __float2half(o0);
                    atth[ab + 512]  = __float2half(o1);
                    atth[ab + 1024] = __float2half(o2);
                    atth[ab + 1536] = __float2half(o3);
                }
            }
        }
    }
}

// ---------------- tensor-core persistent GRU scan (cluster-8, bf16 3-term) ----------------
#define ABST 264
#define ABUF (16 * ABST)
#define OFF_BHI 0
#define OFF_BLO (96 * ABST * 2)
#define OFF_A   (OFF_BLO + 96 * ABST * 2)
#define OFF_GHS (OFF_A + 4 * ABUF * 2)
#define OFF_GIS (OFF_GHS + 16 * 104 * 4)
#define SCAN2_SMEM (OFF_GIS + 16 * 104 * 4)

__global__ void __cluster_dims__(8, 1, 1) __launch_bounds__(256)
gru_scan_mma(const float* __restrict__ gi, const float* __restrict__ whh,
             const float* __restrict__ bhh, float* __restrict__ seqout,
             __half* __restrict__ seqh, int S)
{
    extern __shared__ char smraw[];
    __nv_bfloat16* Bhi = (__nv_bfloat16*)(smraw + OFF_BHI);
    __nv_bfloat16* Blo = (__nv_bfloat16*)(smraw + OFF_BLO);
    __nv_bfloat16* Ab  = (__nv_bfloat16*)(smraw + OFF_A);
    float* ghs = (float*)(smraw + OFF_GHS);
    float* gis = (float*)(smraw + OFF_GIS);

    const int tid = threadIdx.x;
    const int wid = tid >> 5, lane = tid & 31;
    const int j0 = blockIdx.x * 32;
    const int m0 = blockIdx.y * 16;
    const int dd = m0 / S;
    const int jj = tid & 31, j = j0 + jj;
    const int r0 = (tid >> 5) * 2;

    const float* wb = whh + (size_t)dd * G3 * HIDN;
    for (int task = tid; task < 96 * 32; task += 256) {
        int row = task >> 5, grp = task & 31;
        int g = row >> 5, cc = row & 31;
        const float* src = wb + (size_t)(g * 256 + j0 + cc) * HIDN + grp * 8;
        float f[8];
        *(float4*)&f[0] = *(const float4*)src;
        *(float4*)&f[4] = *(const float4*)(src + 4);
        uint4 hi, lo; split8(f, hi, lo);
        *(uint4*)&Bhi[row * ABST + grp * 8] = hi;
        *(uint4*)&Blo[row * ABST + grp * 8] = lo;
    }
    for (int i = tid; i < 4 * ABUF / 2; i += 256)
        ((uint32_t*)Ab)[i] = 0;

    const float b0 = bhh[(size_t)dd * G3 + j];
    const float b1 = bhh[(size_t)dd * G3 + 256 + j];
    const float b2 = bhh[(size_t)dd * G3 + 512 + j];

    uint32_t abase = (uint32_t)__cvta_generic_to_shared(Ab);
    uint32_t peer[8];
#pragma unroll
    for (int rk = 0; rk < 8; rk++)
        asm volatile("mapa.shared::cluster.u32 %0, %1, %2;" : "=r"(peer[rk]) : "r"(abase), "r"(rk));

    const int lrow = ((lane >> 3) & 1) * 8 + (lane & 7);
    const int lk8 = (lane >> 4) * 8;

    cluster_sync_();

    for (int t = 0; t < TT; t++) {
        const int cur = t & 1, nxt = cur ^ 1;
        const int tq = dd ? (TT - 1 - t) : t;

        if (wid < 6) {
            const __nv_bfloat16* Ahi = Ab + (cur * 2 + 0) * ABUF;
            const __nv_bfloat16* Alo = Ab + (cur * 2 + 1) * ABUF;
            float acc[2][4] = {{0,0,0,0},{0,0,0,0}};
#pragma unroll
            for (int kt = 0; kt < 16; kt++) {
                uint32_t aF[2][4], bF[2][4];
                uint32_t adh = (uint32_t)__cvta_generic_to_shared(
                    &Ahi[lrow * ABST + kt * 16 + lk8]);
                uint32_t adl = (uint32_t)__cvta_generic_to_shared(
                    &Alo[lrow * ABST + kt * 16 + lk8]);
                LDMX4(aF[0][0], aF[0][1], aF[0][2], aF[0][3], adh);
                LDMX4(aF[1][0], aF[1][1], aF[1][2], aF[1][3], adl);
                uint32_t bdh = (uint32_t)__cvta_generic_to_shared(
                    &Bhi[(wid * 16 + lrow) * ABST + kt * 16 + lk8]);
                uint32_t bdl = (uint32_t)__cvta_generic_to_shared(
                    &Blo[(wid * 16 + lrow) * ABST + kt * 16 + lk8]);
                LDMX4(bF[0][0], bF[0][1], bF[0][2], bF[0][3], bdh);
                LDMX4(bF[1][0], bF[1][1], bF[1][2], bF[1][3], bdl);
#pragma unroll
                for (int term = 0; term < 3; term++) {
                    const int sa = (term == 2) ? 1 : 0;
                    const int sb = (term == 1) ? 1 : 0;
#pragma unroll
                    for (int nj = 0; nj < 2; nj++)
                        MMABF(acc[nj][0], acc[nj][1], acc[nj][2], acc[nj][3],
                              aF[sa][0], aF[sa][1], aF[sa][2], aF[sa][3],
                              bF[sb][nj], bF[sb][2 + nj]);
                }
            }
            int gr = lane >> 2, c2 = (lane & 3) * 2;
#pragma unroll
            for (int nj = 0; nj < 2; nj++) {
                int col = wid * 16 + nj * 8 + c2;
                *(float2*)&ghs[gr * 104 + col] = make_float2(acc[nj][0], acc[nj][1]);
                *(float2*)&ghs[(gr + 8) * 104 + col] = make_float2(acc[nj][2], acc[nj][3]);
            }
        } else {
            int l2 = (wid - 6) * 32 + lane;
#pragma unroll
            for (int u = 0; u < 6; u++) {
                int f = l2 + u * 64;
                int seg = f >> 3, q = f & 7;
                int s = seg / 3, g = seg % 3;
                float4 v = *(const float4*)(gi + (size_t)(m0 + s) * TT * G3 +
                                            (size_t)tq * G3 + g * 256 + j0 + q * 4);
                *(float4*)&gis[s * 104 + g * 32 + q * 4] = v;
            }
        }
        __syncthreads();

        const __nv_bfloat16* AhiC = Ab + (cur * 2 + 0) * ABUF;
        const __nv_bfloat16* AloC = Ab + (cur * 2 + 1) * ABUF;
        const uint32_t offHiB = (uint32_t)(nxt * 2 * ABUF) * 2;
        const uint32_t offLoB = offHiB + ABUF * 2;
#pragma unroll
        for (int r = 0; r < 2; r++) {
            int s = r0 + r;
            float ir  = gis[s * 104 + jj];
            float iz  = gis[s * 104 + 32 + jj];
            float inn = gis[s * 104 + 64 + jj];
            float gr_ = ghs[s * 104 + jj];
            float gz_ = ghs[s * 104 + 32 + jj];
            float gn_ = ghs[s * 104 + 64 + jj];
            float rg = sigm(ir + gr_ + b0);
            float zg = sigm(iz + gz_ + b1);
            float ng = tanhf(inn + rg * (gn_ + b2));
            float hold = __bfloat162float(AhiC[s * ABST + j]) +
                         __bfloat162float(AloC[s * ABST + j]);
            float hnew = (1.f - zg) * ng + zg * hold;
            int sidx = m0 + s - dd * S;
            size_t so = ((size_t)sidx * TT + tq) * D2 + dd * HIDN + j;
            seqout[so] = hnew;
            seqh[so] = __float2half(hnew);
            __nv_bfloat16 hh = __float2bfloat16(hnew);
            __nv_bfloat16 hl = __float2bfloat16(hnew - __bfloat162float(hh));
            uint16_t vh = __bfloat16_as_ushort(hh), vl = __bfloat16_as_ushort(hl);
            uint32_t eo = (uint32_t)(s * ABST + j) * 2;
#pragma unroll
            for (int rk = 0; rk < 8; rk++) {
                asm volatile("st.shared::cluster.u16 [%0], %1;"
                             :: "r"(peer[rk] + offHiB + eo), "h"(vh) : "memory");
                asm volatile("st.shared::cluster.u16 [%0], %1;"
                             :: "r"(peer[rk] + offLoB + eo), "h"(vl) : "memory");
            }
        }
        cluster_sync_();
    }
}

// ---------------- BiDAF prep / softmax / q2c / rank ----------------
__global__ void __launch_bounds__(256) bidaf_prep(
    const float* __restrict__ cbase, const float* __restrict__ qbase,
    const float* __restrict__ w)
{
    __shared__ float red[256];
    int i = blockIdx.x, z = blockIdx.y, tid = threadIdx.x;
    const float* c = cbase + ((size_t)z * TT + i) * D2;
    const float* q = qbase + ((size_t)z * TT + i) * D2;
    float c0 = c[tid], c1 = c[tid + 256];
    float q0 = q[tid], q1 = q[tid + 256];
    float sc = c0 * w[tid] + c1 * w[tid + 256];
    float sq = q0 * w[512 + tid] + q1 * w[768 + tid];
    float cs0 = c0 * w[1024 + tid];
    float cs1 = c1 * w[1280 + tid];
    size_t ci = ((size_t)z * TT + i) * D2 + tid;
    g_csch[ci] = __float2half(cs0);
    g_csch[ci + 256] = __float2half(cs1);
    float rc = blk_sum(sc, red);
    float rq = blk_sum(sq, red);
    if (tid == 0) { g_cw[z * TT + i] = rc; g_qw[z * TT + i] = rq; }
}

__global__ void __launch_bounds__(256) softmax_row()
{
    __shared__ float red[256];
    int i = blockIdx.x, z = blockIdx.y, tid = threadIdx.x;
    const float* row = g_Sc + ((size_t)z * TT + i) * TT;
    float v = row[tid];
    float mx = blk_max(v, red);
    float e = __expf(v - mx);
    float sm = blk_sum(e, red);
    float p = e / sm;
    g_sch[((size_t)z * TT + i) * TT + tid] = __float2half(p);
    if (tid == 0) g_mrow[z * TT + i] = mx;
}

__global__ void __launch_bounds__(256) q2c_kern(const float* __restrict__ cbase)
{
    __shared__ float red[256];
    __shared__ float bbuf[256];
    int z = blockIdx.x, tid = threadIdx.x;
    float v = g_mrow[z * TT + tid];
    float mx = blk_max(v, red);
    float e = __expf(v - mx);
    float sm = blk_sum(e, red);
    bbuf[tid] = e / sm;
    __syncthreads();
    const float* c = cbase + (size_t)z * TT * D2;
    float a0 = 0.f, a1 = 0.f;
    for (int i = 0; i < TT; i++) {
        float b = bbuf[i];
        a0 += b * c[(size_t)i * D2 + tid];
        a1 += b * c[(size_t)i * D2 + tid + 256];
    }
    g_q2c[(size_t)z * D2 + tid] = a0;
    g_q2c[(size_t)z * D2 + tid + 256] = a1;
}

__global__ void __launch_bounds__(256) rank_partial(const float* __restrict__ rw)
{
    __shared__ float red[256];
    int chunk = blockIdx.x, bo = blockIdx.y, tid = threadIdx.x;
    const float* s0 = g_att + (size_t)(bo * 2) * TT * D8;
    const float* s1 = g_att + (size_t)(bo * 2 + 1) * TT * D8;
    float acc = 0.f;
    int e0 = chunk * 8192 + tid;
#pragma unroll 4
    for (int it = 0; it < 32; it++) {
        int e = e0 + it * 256;
        acc += fmaxf(s0[e], s1[e]) * rw[e];
    }
    float r = blk_sum(acc, red);
    if (tid == 0) g_part[bo * 64 + chunk] = r;
}

__global__ void rank_final(const float* __restrict__ rb, float* __restrict__ out)
{
    __shared__ float red[64];
    int bo = blockIdx.x, tid = threadIdx.x;
    red[tid] = g_part[bo * 64 + tid];
    __syncthreads();
    for (int o = 32; o > 0; o >>= 1) {
        if (tid < o) red[tid] += red[tid + o];
        __syncthreads();
    }
    if (tid == 0) out[bo] = red[0] + rb[0];
}

// ---------------- host ----------------
extern "C" void kernel_launch(void* const* d_in, const int* in_sizes, int n_in,
                              void* d_out, int out_size)
{
    const int*   question = (const int*)d_in[0];
    const int*   article  = (const int*)d_in[1];
    const float* emb      = (const float*)d_in[2];
    const float* g1_wih   = (const float*)d_in[3];
    const float* g1_whh   = (const float*)d_in[4];
    const float* g1_bih   = (const float*)d_in[5];
    const float* g1_bhh   = (const float*)d_in[6];
    const float* g2_wih   = (const float*)d_in[7];
    const float* g2_whh   = (const float*)d_in[8];
    const float* g2_bih   = (const float*)d_in[9];
    const float* g2_bhh   = (const float*)d_in[10];
    const float* b1_w     = (const float*)d_in[11];
    const float* b1_b     = (const float*)d_in[12];
    const float* b2_w     = (const float*)d_in[13];
    const float* b2_b     = (const float*)d_in[14];
    const float* rank_w   = (const float*)d_in[15];
    const float* rank_b   = (const float*)d_in[16];
    float* out = (float*)d_out;

    float *gi1, *gi2, *hcat, *h2out, *att, *Sc, *cwp, *qwp;
    __half *xh, *w1h, *w2h, *hch, *h2h, *csch, *sch, *atth;
    cudaGetSymbolAddress((void**)&gi1,  g_gi1);
    cudaGetSymbolAddress((void**)&gi2,  g_gi2);
    cudaGetSymbolAddress((void**)&hcat, g_hcat);
    cudaGetSymbolAddress((void**)&h2out,g_h2out);
    cudaGetSymbolAddress((void**)&att,  g_att);
    cudaGetSymbolAddress((void**)&Sc,   g_Sc);
    cudaGetSymbolAddress((void**)&cwp,  g_cw);
    cudaGetSymbolAddress((void**)&qwp,  g_qw);
    cudaGetSymbolAddress((void**)&xh,   g_xh);
    cudaGetSymbolAddress((void**)&w1h,  g_w1h);
    cudaGetSymbolAddress((void**)&w2h,  g_w2h);
    cudaGetSymbolAddress((void**)&hch,  g_hch);
    cudaGetSymbolAddress((void**)&h2h,  g_h2h);
    cudaGetSymbolAddress((void**)&csch, g_csch);
    cudaGetSymbolAddress((void**)&sch,  g_sch);
    cudaGetSymbolAddress((void**)&atth, g_atth);

    cudaFuncSetAttribute(gru_scan_mma, cudaFuncAttributeMaxDynamicSharedMemorySize, SCAN2_SMEM);
    cudaFuncSetAttribute(gemm_hf, cudaFuncAttributeMaxDynamicSharedMemorySize, GH_SMEM);
    cudaFuncSetAttribute(gemm_c2q_h, cudaFuncAttributeMaxDynamicSharedMemorySize, C2Q_SMEM);

    // 0. weight conversion
    conv_w<<<(int)((PL_W1 + 255) / 256), 256>>>(g1_wih, w1h, (int)PL_W1);
    conv_w<<<(int)((PL_W2 + 255) / 256), 256>>>(g2_wih, w2h, (int)PL_W2);

    // 1. embed
    gather_embed<<<dim3(TT, S1), 256>>>(question, article, emb);

    // 2. gi1 = xcat @ wih1^T + bih1 (z folded into N)
    gemm_hf<<<dim3(2*G3/128, (S1*TT)/128, 1), 256, GH_SMEM>>>(
        xh, 0LL, w1h, 0LL,
        gi1, (long long)S1*TT*G3, 2*G3, HIDN, G3,
        g1_bih, G3, nullptr, nullptr, nullptr);

    // 3. layer-1 scan
    gru_scan_mma<<<dim3(8, M1/16), 256, SCAN2_SMEM>>>(
        gi1, g1_whh, g1_bhh, hcat, hch, S1);

    // 4. BiDAF1
    const float* cb1 = hcat;
    const long long qoff = (long long)64 * TT * D2;
    bidaf_prep<<<dim3(TT, S2), 256>>>(cb1, hcat + qoff, b1_w);
    gemm_hf<<<dim3(TT/128, TT/128, S2), 256, GH_SMEM>>>(
        csch, (long long)TT*D2, hch + qoff, (long long)TT*D2,
        Sc, (long long)TT*TT, TT, D2, 0,
        nullptr, 0, cwp, qwp, b1_b);
    softmax_row<<<dim3(TT, S2), 256>>>();
    q2c_kern<<<S2, 256>>>(cb1);
    gemm_c2q_h<<<dim3(D2/64, TT/128, S2), 256, C2Q_SMEM>>>(
        sch, hch + qoff, (long long)TT*D2,
        cb1, (long long)TT*D2, att, atth, 0);

    // 5. gi2 = att @ wih2^T + bih2 (z folded)
    gemm_hf<<<dim3(2*G3/128, (S2*TT)/128, 1), 256, GH_SMEM>>>(
        atth, 0LL, w2h, 0LL,
        gi2, (long long)S2*TT*G3, 2*G3, D8, G3,
        g2_bih, G3, nullptr, nullptr, nullptr);

    // 6. layer-2 scan
    gru_scan_mma<<<dim3(8, M2/16), 256, SCAN2_SMEM>>>(
        gi2, g2_whh, g2_bhh, h2out, h2h, S2);

    // 7. BiDAF2
    bidaf_prep<<<dim3(TT, S2), 256>>>(h2out, h2out, b2_w);
    gemm_hf<<<dim3(TT/128, TT/128, S2), 256, GH_SMEM>>>(
        csch, (long long)TT*D2, h2h, (long long)TT*D2,
        Sc, (long long)TT*TT, TT, D2, 0,
        nullptr, 0, cwp, qwp, b2_b);
    softmax_row<<<dim3(TT, S2), 256>>>();
    q2c_kern<<<S2, 256>>>(h2out);
    gemm_c2q_h<<<dim3(D2/64, TT/128, S2), 256, C2Q_SMEM>>>(
        sch, h2h, (long long)TT*D2,
        h2out, (long long)TT*D2, att, atth, 1);

    // 8. rank
    rank_partial<<<dim3(64, 32), 256>>>(rank_w);
    rank_final<<<32, 64>>>(rank_b, out);
}

// round 16
// speedup vs baseline: 1.5770x; 1.4410x over previous
#include <cuda_runtime.h>
#include <cuda_bf16.h>
#include <cuda_fp16.h>
#include <math.h>
#include <stdint.h>

#define TT 256
#define HIDN 256
#define G3 768
#define D2 512
#define D8 2048
#define S1 128
#define S2 64
#define M1 256
#define M2 128

#define PL_X   ((size_t)S1*TT*HIDN)
#define PL_W1  ((size_t)2*G3*HIDN)
#define PL_W2  ((size_t)2*G3*D8)
#define PL_HC  ((size_t)S1*TT*D2)
#define PL_H2  ((size_t)S2*TT*D2)
#define PL_CSC ((size_t)S2*TT*D2)
#define PL_SC  ((size_t)S2*TT*TT)
#define PL_ATT ((size_t)S2*TT*D8)

// ---------------- static device scratch ----------------
__device__ float g_gi1  [(size_t)2*S1*TT*G3];
__device__ float g_hcat [(size_t)S1*TT*D2];
__device__ float g_h2out[(size_t)S2*TT*D2];
__device__ float g_gi2  [(size_t)2*S2*TT*G3];
__device__ float g_att  [(size_t)S2*TT*D8];
__device__ float g_Sc   [(size_t)S2*TT*TT];
__device__ float g_cw   [S2*TT];
__device__ float g_qw   [S2*TT];
__device__ float g_mrow [S2*TT];
__device__ float g_q2c  [S2*D2];
__device__ float g_part [32*64];

__device__ __half g_xh   [PL_X];
__device__ __half g_w1h  [PL_W1];
__device__ __half g_w2h  [PL_W2];
__device__ __half g_hch  [PL_HC];
__device__ __half g_h2h  [PL_H2];
__device__ __half g_csch [PL_CSC];
__device__ __half g_sch  [PL_SC];
__device__ __half g_atth [PL_ATT];

// ---------------- generic helpers ----------------
__device__ __forceinline__ float blk_sum(float v, float* red) {
    int t = threadIdx.x;
    red[t] = v; __syncthreads();
    for (int o = blockDim.x >> 1; o > 0; o >>= 1) {
        if (t < o) red[t] += red[t + o];
        __syncthreads();
    }
    float r = red[0]; __syncthreads();
    return r;
}
__device__ __forceinline__ float blk_max(float v, float* red) {
    int t = threadIdx.x;
    red[t] = v; __syncthreads();
    for (int o = blockDim.x >> 1; o > 0; o >>= 1) {
        if (t < o) red[t] = fmaxf(red[t], red[t + o]);
        __syncthreads();
    }
    float r = red[0]; __syncthreads();
    return r;
}
__device__ __forceinline__ float sigm(float x) { return 1.f / (1.f + __expf(-x)); }

__device__ __forceinline__ void cluster_sync_() {
    asm volatile("barrier.cluster.arrive.aligned;" ::: "memory");
    asm volatile("barrier.cluster.wait.aligned;" ::: "memory");
}

__device__ __forceinline__ uint32_t pkh2(__half a, __half b) {
    return (uint32_t)__half_as_ushort(a) | ((uint32_t)__half_as_ushort(b) << 16);
}
__device__ __forceinline__ uint4 cvt8h(const float* f) {
    return make_uint4(
        pkh2(__float2half(f[0]), __float2half(f[1])),
        pkh2(__float2half(f[2]), __float2half(f[3])),
        pkh2(__float2half(f[4]), __float2half(f[5])),
        pkh2(__float2half(f[6]), __float2half(f[7])));
}

#define LDMX4(r0,r1,r2,r3,addr) \
    asm volatile("ldmatrix.sync.aligned.m8n8.x4.shared.b16 {%0,%1,%2,%3}, [%4];" \
        : "=r"(r0), "=r"(r1), "=r"(r2), "=r"(r3) : "r"(addr))
#define LDMX4T(r0,r1,r2,r3,addr) \
    asm volatile("ldmatrix.sync.aligned.m8n8.x4.trans.shared.b16 {%0,%1,%2,%3}, [%4];" \
        : "=r"(r0), "=r"(r1), "=r"(r2), "=r"(r3) : "r"(addr))

#define MMAHF(c0,c1,c2,c3,a0,a1,a2,a3,b0,b1) \
    asm volatile("mma.sync.aligned.m16n8k16.row.col.f32.f16.f16.f32 " \
        "{%0,%1,%2,%3}, {%4,%5,%6,%7}, {%8,%9}, {%0,%1,%2,%3};" \
        : "+f"(c0), "+f"(c1), "+f"(c2), "+f"(c3) \
        : "r"(a0), "r"(a1), "r"(a2), "r"(a3), "r"(b0), "r"(b1))

#define CPA16(dst, src) \
    asm volatile("cp.async.cg.shared.global [%0], [%1], 16;" :: "r"(dst), "l"(src))
#define CPA_COMMIT() asm volatile("cp.async.commit_group;" ::: "memory")
#define CPA_WAIT0()  asm volatile("cp.async.wait_group 0;" ::: "memory")
#define CPA_WAIT1()  asm volatile("cp.async.wait_group 1;" ::: "memory")
#define CPA_WAIT2()  asm volatile("cp.async.wait_group 2;" ::: "memory")

__device__ __forceinline__ void cpa_wait_rem(int rem) {
    if (rem >= 2) CPA_WAIT2();
    else if (rem == 1) CPA_WAIT1();
    else CPA_WAIT0();
}

// ---------------- conversion kernels ----------------
__global__ void conv_w(const float* __restrict__ w, __half* __restrict__ dst, int n)
{
    int i = blockIdx.x * 256 + threadIdx.x;
    if (i < n) dst[i] = __float2half(w[i]);
}

__global__ void __launch_bounds__(256) gather_embed(
    const int* __restrict__ q, const int* __restrict__ a,
    const float* __restrict__ emb)
{
    int t = blockIdx.x, s = blockIdx.y, tid = threadIdx.x;
    int id = (s < 64) ? q[(s >> 1) * TT + t] : a[(size_t)(s - 64) * TT + t];
    float v = emb[(size_t)id * HIDN + tid];
    g_xh[((size_t)s * TT + t) * HIDN + tid] = __float2half(v);
}

// ---------------- 4-stage pipelined fp16 MMA GEMM, BM=128 BN=128 ----------------
#define SKP 40
#define PLANEH (128 * SKP)
#define STAGEH (2 * PLANEH)
#define GH_SMEM (4 * STAGEH * 2)

__global__ void __launch_bounds__(256, 2) gemm_hf(
    const __half* __restrict__ Ab, long long sA,
    const __half* __restrict__ Wb, long long sW,
    float* __restrict__ Cb, long long sC,
    int N, int K, int foldN,
    const float* __restrict__ bias, long long sBias,
    const float* __restrict__ cw, const float* __restrict__ qw,
    const float* __restrict__ bvec)
{
    extern __shared__ __half smx[];
    const int tid = threadIdx.x;
    const int wid = tid >> 5, lane = tid & 31;
    const int z = blockIdx.z;
    const int m0 = blockIdx.y * 128, n0 = blockIdx.x * 128;
    const __half* A = Ab + (size_t)z * sA;
    const __half* W = Wb + (size_t)z * sW;

    const int wm = (wid & 3) * 32;
    const int wn = (wid >> 2) * 64;
    const int nk = K >> 5;

    const int r0 = tid >> 2, cg8 = (tid & 3) * 8;

    float acc[2][8][4];
#pragma unroll
    for (int i = 0; i < 2; i++)
#pragma unroll
        for (int j = 0; j < 8; j++)
#pragma unroll
            for (int qq = 0; qq < 4; qq++) acc[i][j][qq] = 0.f;

    const int lrow = ((lane >> 3) & 1) * 8 + (lane & 7);
    const int lk8 = (lane >> 4) * 8;

    auto issue = [&](int ki) {
        const int k0 = ki * 32;
        __half* Ast = smx + (ki & 3) * STAGEH;
        __half* Bst = Ast + PLANEH;
#pragma unroll
        for (int half_ = 0; half_ < 2; half_++) {
            int r = r0 + half_ * 64;
            size_t ao = (size_t)(m0 + r) * K + k0 + cg8;
            size_t bo = (size_t)(n0 + r) * K + k0 + cg8;
            uint32_t da = (uint32_t)__cvta_generic_to_shared(&Ast[r * SKP + cg8]);
            uint32_t db = (uint32_t)__cvta_generic_to_shared(&Bst[r * SKP + cg8]);
            CPA16(da, A + ao);
            CPA16(db, W + bo);
        }
    };

#pragma unroll
    for (int p = 0; p < 3; p++) {
        if (p < nk) { issue(p); CPA_COMMIT(); }
    }

    for (int ki = 0; ki < nk; ki++) {
        cpa_wait_rem(nk - ki - 1);
        __syncthreads();
        if (ki + 3 < nk) { issue(ki + 3); CPA_COMMIT(); }

        __half* Ast = smx + (ki & 3) * STAGEH;
        __half* Bst = Ast + PLANEH;
#pragma unroll
        for (int kk = 0; kk < 32; kk += 16) {
            uint32_t aF[2][4];
#pragma unroll
            for (int mi = 0; mi < 2; mi++) {
                uint32_t ad = (uint32_t)__cvta_generic_to_shared(
                    &Ast[(wm + mi * 16 + lrow) * SKP + kk + lk8]);
                LDMX4(aF[mi][0], aF[mi][1], aF[mi][2], aF[mi][3], ad);
            }
            uint32_t bF[4][4];
#pragma unroll
            for (int nj2 = 0; nj2 < 4; nj2++) {
                uint32_t ad = (uint32_t)__cvta_generic_to_shared(
                    &Bst[(wn + nj2 * 16 + lrow) * SKP + kk + lk8]);
                LDMX4(bF[nj2][0], bF[nj2][1], bF[nj2][2], bF[nj2][3], ad);
            }
#pragma unroll
            for (int mi = 0; mi < 2; mi++)
#pragma unroll
                for (int nj = 0; nj < 8; nj++) {
                    int nj2 = nj >> 1, odd = nj & 1;
                    MMAHF(acc[mi][nj][0], acc[mi][nj][1], acc[mi][nj][2], acc[mi][nj][3],
                          aF[mi][0], aF[mi][1], aF[mi][2], aF[mi][3],
                          bF[nj2][odd], bF[nj2][2 + odd]);
                }
        }
    }
    const int g = lane >> 2, t4 = lane & 3;
    if (bias) {
        const int zz = (n0 >= foldN) ? 1 : 0;
        const int nb = n0 - zz * foldN;
        float* C = Cb + (size_t)zz * sC;
        const float* bz = bias + (size_t)zz * sBias;
#pragma unroll
        for (int mi = 0; mi < 2; mi++) {
            int mrow = m0 + wm + mi * 16 + g;
#pragma unroll
            for (int nj = 0; nj < 8; nj++) {
                int ncol = nb + wn + nj * 8 + t4 * 2;
                float b0v = bz[ncol];
                float b1v = bz[ncol + 1];
                *(float2*)&C[(size_t)mrow * foldN + ncol] =
                    make_float2(acc[mi][nj][0] + b0v, acc[mi][nj][1] + b1v);
                *(float2*)&C[(size_t)(mrow + 8) * foldN + ncol] =
                    make_float2(acc[mi][nj][2] + b0v, acc[mi][nj][3] + b1v);
            }
        }
    } else {
        float* C = Cb + (size_t)z * sC;
        float badd = bvec[0] + bvec[1] + bvec[2];
#pragma unroll
        for (int mi = 0; mi < 2; mi++) {
            int mrow = m0 + wm + mi * 16 + g;
            float cw0 = cw[(size_t)z * TT + mrow] + badd;
            float cw1 = cw[(size_t)z * TT + mrow + 8] + badd;
#pragma unroll
            for (int nj = 0; nj < 8; nj++) {
                int ncol = n0 + wn + nj * 8 + t4 * 2;
                float q0v = qw[(size_t)z * TT + ncol];
                float q1v = qw[(size_t)z * TT + ncol + 1];
                *(float2*)&C[(size_t)mrow * N + ncol] =
                    make_float2(acc[mi][nj][0] + cw0 + q0v, acc[mi][nj][1] + cw0 + q1v);
                *(float2*)&C[(size_t)(mrow + 8) * N + ncol] =
                    make_float2(acc[mi][nj][2] + cw1 + q0v, acc[mi][nj][3] + cw1 + q1v);
            }
        }
    }
}

// ---------------- 4-stage pipelined c2q fp16 + BiDAF epilogue ----------------
#define C2_AST (128 * SKP)
#define BKP 72
#define B2ST (32 * BKP)
#define C2STAGE (C2_AST + B2ST)
#define C2Q_SMEM (4 * C2STAGE * 2)

__global__ void __launch_bounds__(256) gemm_c2q_h(
    const __half* __restrict__ Ab,
    const __half* __restrict__ Bb, long long sB,
    const float* __restrict__ cb, long long sCrow,
    float* __restrict__ outb, __half* __restrict__ atth, int addMode)
{
    extern __shared__ __half smx[];
    const int tid = threadIdx.x;
    const int wid = tid >> 5, lane = tid & 31;
    const int z = blockIdx.z;
    const int m0 = blockIdx.y * 128, n0 = blockIdx.x * 64;
    const __half* A = Ab + (size_t)z * TT * TT;
    const __half* B = Bb + (size_t)z * sB;
    const float* c = cb + (size_t)z * sCrow;
    const float* qc = g_q2c + (size_t)z * D2;
    float* out = outb + (size_t)z * TT * D8;

    const int wm = (wid & 3) * 32;
    const int wn = (wid >> 2) * 32;
    const int nk = TT >> 5;

    float acc[2][4][4];
#pragma unroll
    for (int i = 0; i < 2; i++)
#pragma unroll
        for (int j = 0; j < 4; j++)
#pragma unroll
            for (int qq = 0; qq < 4; qq++) acc[i][j][qq] = 0.f;

    const int lrow = ((lane >> 3) & 1) * 8 + (lane & 7);
    const int lk8 = (lane >> 4) * 8;
    const int lkrow = (lane & 7) + ((lane >> 4) << 3);
    const int lncol = ((lane >> 3) & 1) * 8;

    const int ar0 = tid >> 2, acg = (tid & 3) * 8;
    const int bkr = tid >> 3, bnc = (tid & 7) * 8;

    auto issue = [&](int ki) {
        const int k0 = ki * 32;
        __half* Ast = smx + (ki & 3) * C2STAGE;
        __half* Bst = Ast + C2_AST;
#pragma unroll
        for (int half_ = 0; half_ < 2; half_++) {
            int r = ar0 + half_ * 64;
            size_t so = (size_t)(m0 + r) * TT + k0 + acg;
            uint32_t d = (uint32_t)__cvta_generic_to_shared(&Ast[r * SKP + acg]);
            CPA16(d, A + so);
        }
        {
            size_t so = (size_t)(k0 + bkr) * D2 + n0 + bnc;
            uint32_t d = (uint32_t)__cvta_generic_to_shared(&Bst[bkr * BKP + bnc]);
            CPA16(d, B + so);
        }
    };

#pragma unroll
    for (int p = 0; p < 3; p++) {
        if (p < nk) { issue(p); CPA_COMMIT(); }
    }

    for (int ki = 0; ki < nk; ki++) {
        cpa_wait_rem(nk - ki - 1);
        __syncthreads();
        if (ki + 3 < nk) { issue(ki + 3); CPA_COMMIT(); }

        __half* Ast = smx + (ki & 3) * C2STAGE;
        __half* Bst = Ast + C2_AST;
#pragma unroll
        for (int kk = 0; kk < 32; kk += 16) {
            uint32_t aF[2][4], bF[2][4];
#pragma unroll
            for (int mi = 0; mi < 2; mi++) {
                uint32_t ad = (uint32_t)__cvta_generic_to_shared(
                    &Ast[(wm + mi * 16 + lrow) * SKP + kk + lk8]);
                LDMX4(aF[mi][0], aF[mi][1], aF[mi][2], aF[mi][3], ad);
            }
#pragma unroll
            for (int nj2 = 0; nj2 < 2; nj2++) {
                uint32_t ad = (uint32_t)__cvta_generic_to_shared(
                    &Bst[(kk + lkrow) * BKP + wn + nj2 * 16 + lncol]);
                LDMX4T(bF[nj2][0], bF[nj2][1], bF[nj2][2], bF[nj2][3], ad);
            }
#pragma unroll
            for (int mi = 0; mi < 2; mi++)
#pragma unroll
                for (int nj = 0; nj < 4; nj++) {
                    int nj2 = nj >> 1, odd = nj & 1;
                    MMAHF(acc[mi][nj][0], acc[mi][nj][1], acc[mi][nj][2], acc[mi][nj][3],
                          aF[mi][0], aF[mi][1], aF[mi][2], aF[mi][3],
                          bF[nj2][odd], bF[nj2][2 + odd]);
                }
        }
    }
    const int g = lane >> 2, t4 = lane & 3;
#pragma unroll
    for (int mi = 0; mi < 2; mi++) {
#pragma unroll
        for (int nj = 0; nj < 4; nj++) {
#pragma unroll
            for (int hh = 0; hh < 4; hh++) {
                int mm = m0 + wm + mi * 16 + g + (hh >> 1) * 8;
                int nn = n0 + wn + nj * 8 + t4 * 2 + (hh & 1);
                float c2v = acc[mi][nj][hh];
                float cv = c[(size_t)mm * D2 + nn];
                float o0 = fmaxf(cv, 0.f);
                float o1 = fmaxf(c2v, 0.f);
                float o2 = fmaxf(cv * c2v, 0.f);
                float o3 = fmaxf(cv * qc[nn], 0.f);
                size_t b = (size_t)mm * D8 + nn;
                if (addMode) {
                    out[b] += o0; out[b + 512] += o1;
                    out[b + 1024] += o2; out[b + 1536] += o3;
                } else {
                    out[b] = o0; out[b + 512] = o1;
                    out[b + 1024] = o2; out[b + 1536] = o3;
                    size_t ab = (size_t)z * TT * D8 + b;
                    atth[ab]        = __float2half(o0);
                    atth[ab + 512]  = __float2half(o1);
                    atth[ab + 1024] = __float2half(o2);
                    atth[ab + 1536] = __float2half(o3);
                }
            }
        }
    }
}

// ---------------- tensor-core persistent GRU scan (cluster-8, fp16 single) ----------------
#define ABST 264
#define ABUF (16 * ABST)
#define OFF_BH 0
#define OFF_A   (96 * ABST * 2)
#define OFF_GHS (OFF_A + 2 * ABUF * 2)
#define OFF_GIS (OFF_GHS + 16 * 104 * 4)
#define SCAN3_SMEM (OFF_GIS + 16 * 104 * 4)

__global__ void __cluster_dims__(8, 1, 1) __launch_bounds__(256)
gru_scan_mma(const float* __restrict__ gi, const float* __restrict__ whh,
             const float* __restrict__ bhh, float* __restrict__ seqout,
             __half* __restrict__ seqh, int S)
{
    extern __shared__ char smraw[];
    __half* Bh = (__half*)(smraw + OFF_BH);
    __half* Ab = (__half*)(smraw + OFF_A);
    float* ghs = (float*)(smraw + OFF_GHS);
    float* gis = (float*)(smraw + OFF_GIS);

    const int tid = threadIdx.x;
    const int wid = tid >> 5, lane = tid & 31;
    const int j0 = blockIdx.x * 32;
    const int m0 = blockIdx.y * 16;
    const int dd = m0 / S;
    const int jj = tid & 31, j = j0 + jj;
    const int r0 = (tid >> 5) * 2;

    // load + convert whh slice once (fp16 single plane)
    const float* wb = whh + (size_t)dd * G3 * HIDN;
    for (int task = tid; task < 96 * 32; task += 256) {
        int row = task >> 5, grp = task & 31;
        int g = row >> 5, cc = row & 31;
        const float* src = wb + (size_t)(g * 256 + j0 + cc) * HIDN + grp * 8;
        float f[8];
        *(float4*)&f[0] = *(const float4*)src;
        *(float4*)&f[4] = *(const float4*)(src + 4);
        *(uint4*)&Bh[row * ABST + grp * 8] = cvt8h(f);
    }
    for (int i = tid; i < 2 * ABUF / 2; i += 256)
        ((uint32_t*)Ab)[i] = 0;

    const float b0 = bhh[(size_t)dd * G3 + j];
    const float b1 = bhh[(size_t)dd * G3 + 256 + j];
    const float b2 = bhh[(size_t)dd * G3 + 512 + j];

    uint32_t abase = (uint32_t)__cvta_generic_to_shared(Ab);
    uint32_t peer[8];
#pragma unroll
    for (int rk = 0; rk < 8; rk++)
        asm volatile("mapa.shared::cluster.u32 %0, %1, %2;" : "=r"(peer[rk]) : "r"(abase), "r"(rk));

    const int lrow = ((lane >> 3) & 1) * 8 + (lane & 7);
    const int lk8 = (lane >> 4) * 8;

    cluster_sync_();

    for (int t = 0; t < TT; t++) {
        const int cur = t & 1, nxt = cur ^ 1;
        const int tq = dd ? (TT - 1 - t) : t;

        if (wid < 6) {
            const __half* Ac = Ab + cur * ABUF;
            float acc[2][4] = {{0,0,0,0},{0,0,0,0}};
#pragma unroll
            for (int kt = 0; kt < 16; kt++) {
                uint32_t aF[4], bF[4];
                uint32_t ad = (uint32_t)__cvta_generic_to_shared(
                    &Ac[lrow * ABST + kt * 16 + lk8]);
                LDMX4(aF[0], aF[1], aF[2], aF[3], ad);
                uint32_t bd = (uint32_t)__cvta_generic_to_shared(
                    &Bh[(wid * 16 + lrow) * ABST + kt * 16 + lk8]);
                LDMX4(bF[0], bF[1], bF[2], bF[3], bd);
#pragma unroll
                for (int nj = 0; nj < 2; nj++)
                    MMAHF(acc[nj][0], acc[nj][1], acc[nj][2], acc[nj][3],
                          aF[0], aF[1], aF[2], aF[3],
                          bF[nj], bF[2 + nj]);
            }
            int gr = lane >> 2, c2 = (lane & 3) * 2;
#pragma unroll
            for (int nj = 0; nj < 2; nj++) {
                int col = wid * 16 + nj * 8 + c2;
                *(float2*)&ghs[gr * 104 + col] = make_float2(acc[nj][0], acc[nj][1]);
                *(float2*)&ghs[(gr + 8) * 104 + col] = make_float2(acc[nj][2], acc[nj][3]);
            }
        } else {
            int l2 = (wid - 6) * 32 + lane;
#pragma unroll
            for (int u = 0; u < 6; u++) {
                int f = l2 + u * 64;
                int seg = f >> 3, q = f & 7;
                int s = seg / 3, g = seg % 3;
                float4 v = *(const float4*)(gi + (size_t)(m0 + s) * TT * G3 +
                                            (size_t)tq * G3 + g * 256 + j0 + q * 4);
                *(float4*)&gis[s * 104 + g * 32 + q * 4] = v;
            }
        }
        __syncthreads();

        const __half* AcC = Ab + cur * ABUF;
        const uint32_t offNB = (uint32_t)(nxt * ABUF) * 2;
#pragma unroll
        for (int r = 0; r < 2; r++) {
            int s = r0 + r;
            float ir  = gis[s * 104 + jj];
            float iz  = gis[s * 104 + 32 + jj];
            float inn = gis[s * 104 + 64 + jj];
            float gr_ = ghs[s * 104 + jj];
            float gz_ = ghs[s * 104 + 32 + jj];
            float gn_ = ghs[s * 104 + 64 + jj];
            float rg = sigm(ir + gr_ + b0);
            float zg = sigm(iz + gz_ + b1);
            float ng = tanhf(inn + rg * (gn_ + b2));
            float hold = __half2float(AcC[s * ABST + j]);
            float hnew = (1.f - zg) * ng + zg * hold;
            int sidx = m0 + s - dd * S;
            size_t so = ((size_t)sidx * TT + tq) * D2 + dd * HIDN + j;
            seqout[so] = hnew;
            __half hh = __float2half(hnew);
            seqh[so] = hh;
            uint16_t vh = __half_as_ushort(hh);
            uint32_t eo = (uint32_t)(s * ABST + j) * 2;
#pragma unroll
            for (int rk = 0; rk < 8; rk++) {
                asm volatile("st.shared::cluster.u16 [%0], %1;"
                             :: "r"(peer[rk] + offNB + eo), "h"(vh) : "memory");
            }
        }
        cluster_sync_();
    }
}

// ---------------- BiDAF prep / softmax / q2c / rank ----------------
__global__ void __launch_bounds__(256) bidaf_prep(
    const float* __restrict__ cbase, const float* __restrict__ qbase,
    const float* __restrict__ w)
{
    __shared__ float red[256];
    int i = blockIdx.x, z = blockIdx.y, tid = threadIdx.x;
    const float* c = cbase + ((size_t)z * TT + i) * D2;
    const float* q = qbase + ((size_t)z * TT + i) * D2;
    float c0 = c[tid], c1 = c[tid + 256];
    float q0 = q[tid], q1 = q[tid + 256];
    float sc = c0 * w[tid] + c1 * w[tid + 256];
    float sq = q0 * w[512 + tid] + q1 * w[768 + tid];
    float cs0 = c0 * w[1024 + tid];
    float cs1 = c1 * w[1280 + tid];
    size_t ci = ((size_t)z * TT + i) * D2 + tid;
    g_csch[ci] = __float2half(cs0);
    g_csch[ci + 256] = __float2half(cs1);
    float rc = blk_sum(sc, red);
    float rq = blk_sum(sq, red);
    if (tid == 0) { g_cw[z * TT + i] = rc; g_qw[z * TT + i] = rq; }
}

__global__ void __launch_bounds__(256) softmax_row()
{
    __shared__ float red[256];
    int i = blockIdx.x, z = blockIdx.y, tid = threadIdx.x;
    const float* row = g_Sc + ((size_t)z * TT + i) * TT;
    float v = row[tid];
    float mx = blk_max(v, red);
    float e = __expf(v - mx);
    float sm = blk_sum(e, red);
    float p = e / sm;
    g_sch[((size_t)z * TT + i) * TT + tid] = __float2half(p);
    if (tid == 0) g_mrow[z * TT + i] = mx;
}

__global__ void __launch_bounds__(256) q2c_kern(const float* __restrict__ cbase)
{
    __shared__ float red[256];
    __shared__ float bbuf[256];
    int z = blockIdx.x, tid = threadIdx.x;
    float v = g_mrow[z * TT + tid];
    float mx = blk_max(v, red);
    float e = __expf(v - mx);
    float sm = blk_sum(e, red);
    bbuf[tid] = e / sm;
    __syncthreads();
    const float* c = cbase + (size_t)z * TT * D2;
    float a0 = 0.f, a1 = 0.f;
    for (int i = 0; i < TT; i++) {
        float b = bbuf[i];
        a0 += b * c[(size_t)i * D2 + tid];
        a1 += b * c[(size_t)i * D2 + tid + 256];
    }
    g_q2c[(size_t)z * D2 + tid] = a0;
    g_q2c[(size_t)z * D2 + tid + 256] = a1;
}

__global__ void __launch_bounds__(256) rank_partial(const float* __restrict__ rw)
{
    __shared__ float red[256];
    int chunk = blockIdx.x, bo = blockIdx.y, tid = threadIdx.x;
    const float* s0 = g_att + (size_t)(bo * 2) * TT * D8;
    const float* s1 = g_att + (size_t)(bo * 2 + 1) * TT * D8;
    float acc = 0.f;
    int e0 = chunk * 8192 + tid;
#pragma unroll 4
    for (int it = 0; it < 32; it++) {
        int e = e0 + it * 256;
        acc += fmaxf(s0[e], s1[e]) * rw[e];
    }
    float r = blk_sum(acc, red);
    if (tid == 0) g_part[bo * 64 + chunk] = r;
}

__global__ void rank_final(const float* __restrict__ rb, float* __restrict__ out)
{
    __shared__ float red[64];
    int bo = blockIdx.x, tid = threadIdx.x;
    red[tid] = g_part[bo * 64 + tid];
    __syncthreads();
    for (int o = 32; o > 0; o >>= 1) {
        if (tid < o) red[tid] += red[tid + o];
        __syncthreads();
    }
    if (tid == 0) out[bo] = red[0] + rb[0];
}

// ---------------- host ----------------
extern "C" void kernel_launch(void* const* d_in, const int* in_sizes, int n_in,
                              void* d_out, int out_size)
{
    const int*   question = (const int*)d_in[0];
    const int*   article  = (const int*)d_in[1];
    const float* emb      = (const float*)d_in[2];
    const float* g1_wih   = (const float*)d_in[3];
    const float* g1_whh   = (const float*)d_in[4];
    const float* g1_bih   = (const float*)d_in[5];
    const float* g1_bhh   = (const float*)d_in[6];
    const float* g2_wih   = (const float*)d_in[7];
    const float* g2_whh   = (const float*)d_in[8];
    const float* g2_bih   = (const float*)d_in[9];
    const float* g2_bhh   = (const float*)d_in[10];
    const float* b1_w     = (const float*)d_in[11];
    const float* b1_b     = (const float*)d_in[12];
    const float* b2_w     = (const float*)d_in[13];
    const float* b2_b     = (const float*)d_in[14];
    const float* rank_w   = (const float*)d_in[15];
    const float* rank_b   = (const float*)d_in[16];
    float* out = (float*)d_out;

    float *gi1, *gi2, *hcat, *h2out, *att, *Sc, *cwp, *qwp;
    __half *xh, *w1h, *w2h, *hch, *h2h, *csch, *sch, *atth;
    cudaGetSymbolAddress((void**)&gi1,  g_gi1);
    cudaGetSymbolAddress((void**)&gi2,  g_gi2);
    cudaGetSymbolAddress((void**)&hcat, g_hcat);
    cudaGetSymbolAddress((void**)&h2out,g_h2out);
    cudaGetSymbolAddress((void**)&att,  g_att);
    cudaGetSymbolAddress((void**)&Sc,   g_Sc);
    cudaGetSymbolAddress((void**)&cwp,  g_cw);
    cudaGetSymbolAddress((void**)&qwp,  g_qw);
    cudaGetSymbolAddress((void**)&xh,   g_xh);
    cudaGetSymbolAddress((void**)&w1h,  g_w1h);
    cudaGetSymbolAddress((void**)&w2h,  g_w2h);
    cudaGetSymbolAddress((void**)&hch,  g_hch);
    cudaGetSymbolAddress((void**)&h2h,  g_h2h);
    cudaGetSymbolAddress((void**)&csch, g_csch);
    cudaGetSymbolAddress((void**)&sch,  g_sch);
    cudaGetSymbolAddress((void**)&atth, g_atth);

    cudaFuncSetAttribute(gru_scan_mma, cudaFuncAttributeMaxDynamicSharedMemorySize, SCAN3_SMEM);
    cudaFuncSetAttribute(gemm_hf, cudaFuncAttributeMaxDynamicSharedMemorySize, GH_SMEM);
    cudaFuncSetAttribute(gemm_c2q_h, cudaFuncAttributeMaxDynamicSharedMemorySize, C2Q_SMEM);

    // 0. weight conversion
    conv_w<<<(int)((PL_W1 + 255) / 256), 256>>>(g1_wih, w1h, (int)PL_W1);
    conv_w<<<(int)((PL_W2 + 255) / 256), 256>>>(g2_wih, w2h, (int)PL_W2);

    // 1. embed
    gather_embed<<<dim3(TT, S1), 256>>>(question, article, emb);

    // 2. gi1 = xcat @ wih1^T + bih1 (z folded into N)
    gemm_hf<<<dim3(2*G3/128, (S1*TT)/128, 1), 256, GH_SMEM>>>(
        xh, 0LL, w1h, 0LL,
        gi1, (long long)S1*TT*G3, 2*G3, HIDN, G3,
        g1_bih, G3, nullptr, nullptr, nullptr);

    // 3. layer-1 scan
    gru_scan_mma<<<dim3(8, M1/16), 256, SCAN3_SMEM>>>(
        gi1, g1_whh, g1_bhh, hcat, hch, S1);

    // 4. BiDAF1
    const float* cb1 = hcat;
    const long long qoff = (long long)64 * TT * D2;
    bidaf_prep<<<dim3(TT, S2), 256>>>(cb1, hcat + qoff, b1_w);
    gemm_hf<<<dim3(TT/128, TT/128, S2), 256, GH_SMEM>>>(
        csch, (long long)TT*D2, hch + qoff, (long long)TT*D2,
        Sc, (long long)TT*TT, TT, D2, 0,
        nullptr, 0, cwp, qwp, b1_b);
    softmax_row<<<dim3(TT, S2), 256>>>();
    q2c_kern<<<S2, 256>>>(cb1);
    gemm_c2q_h<<<dim3(D2/64, TT/128, S2), 256, C2Q_SMEM>>>(
        sch, hch + qoff, (long long)TT*D2,
        cb1, (long long)TT*D2, att, atth, 0);

    // 5. gi2 = att @ wih2^T + bih2 (z folded)
    gemm_hf<<<dim3(2*G3/128, (S2*TT)/128, 1), 256, GH_SMEM>>>(
        atth, 0LL, w2h, 0LL,
        gi2, (long long)S2*TT*G3, 2*G3, D8, G3,
        g2_bih, G3, nullptr, nullptr, nullptr);

    // 6. layer-2 scan
    gru_scan_mma<<<dim3(8, M2/16), 256, SCAN3_SMEM>>>(
        gi2, g2_whh, g2_bhh, h2out, h2h, S2);

    // 7. BiDAF2
    bidaf_prep<<<dim3(TT, S2), 256>>>(h2out, h2out, b2_w);
    gemm_hf<<<dim3(TT/128, TT/128, S2), 256, GH_SMEM>>>(
        csch, (long long)TT*D2, h2h, (long long)TT*D2,
        Sc, (long long)TT*TT, TT, D2, 0,
        nullptr, 0, cwp, qwp, b2_b);
    softmax_row<<<dim3(TT, S2), 256>>>();
    q2c_kern<<<S2, 256>>>(h2out);
    gemm_c2q_h<<<dim3(D2/64, TT/128, S2), 256, C2Q_SMEM>>>(
        sch, h2h, (long long)TT*D2,
        h2out, (long long)TT*D2, att, atth, 1);

    // 8. rank
    rank_partial<<<dim3(64, 32), 256>>>(rank_w);
    rank_final<<<32, 64>>>(rank_b, out);
}